// round 1
// baseline (speedup 1.0000x reference)
#include <cuda_runtime.h>
#include <math.h>
#include <stdint.h>

// Problem constants
#define B_   16
#define H_   64
#define W_   64
#define C_   512
#define NH_  16
#define HD_  32
#define NTOK 65536           // B*H*W
#define NWIN 64              // windows per image
#define NROW 65536           // Bw*N = 1024*64

// ---------------- device scratch (allocation-free) ----------------
__device__ float g_xw[(size_t)NROW * C_];    // windowed input, later attention output
__device__ float g_q [(size_t)NROW * C_];    // q, later proj output y
__device__ float g_k [(size_t)NROW * C_];    // k, later mlp h2
__device__ float g_v [(size_t)NROW * C_];    // v, later x1
__device__ float g_h [(size_t)NROW * 2048];  // mlp hidden
__device__ float g_tbl[225 * 16];            // cpb table

// ---------------- CPB bias table: 225 positions x 16 heads ----------------
__global__ void cpb_kernel(const float* __restrict__ w1, const float* __restrict__ b1,
                           const float* __restrict__ w2, const float* __restrict__ b2,
                           float* __restrict__ tbl)
{
    int f = blockIdx.x;      // 0..224
    int h = threadIdx.x;     // 0..511
    int i = f / 15, j = f % 15;
    float v0 = 8.0f * (float)(j - 7) / 7.0f;   // component 0 (col delta)
    float v1 = 8.0f * (float)(i - 7) / 7.0f;   // component 1 (row delta)
    float c0 = copysignf(log2f(fabsf(v0) + 1.0f) * (1.0f / 3.0f), v0);
    float c1 = copysignf(log2f(fabsf(v1) + 1.0f) * (1.0f / 3.0f), v1);
    float hid = fmaxf(c0 * w1[h] + c1 * w1[512 + h] + b1[h], 0.0f);

    __shared__ float red[512];
    for (int nh = 0; nh < 16; ++nh) {
        red[h] = hid * w2[h * 16 + nh];
        __syncthreads();
        for (int s = 256; s > 0; s >>= 1) {
            if (h < s) red[h] += red[h + s];
            __syncthreads();
        }
        if (h == 0) tbl[f * 16 + nh] = red[0] + b2[nh];
        __syncthreads();
    }
}

// ---------------- shift + window partition gather ----------------
__global__ void gather_xw(const float* __restrict__ x, float* __restrict__ xw)
{
    size_t idx = (size_t)blockIdx.x * 256 + threadIdx.x;   // over float4s
    if (idx >= (size_t)NROW * 128) return;
    int c4  = (int)(idx & 127);
    int row = (int)(idx >> 7);
    int n = row & 63, bw = row >> 6;
    int win = bw & 63, b = bw >> 6;
    int wh = win >> 3, wwn = win & 7;
    int i = n >> 3, j = n & 7;
    int h = ((wh << 3) + i + 4) & 63;    // roll -SHIFT
    int w = ((wwn << 3) + j + 4) & 63;
    const float4* src = (const float4*)(x + (size_t)((b << 12) + (h << 6) + w) * C_) + c4;
    ((float4*)(xw + (size_t)row * C_))[c4] = *src;
}

// ---------------- generic SGEMM: C = A(MxK) * B(KxN) [+bias] [gelu] ----------------
template<int GELU>
__global__ void __launch_bounds__(256) sgemm_kernel(
    const float* __restrict__ A, const float* __restrict__ Bm,
    const float* __restrict__ bias, float* __restrict__ C,
    int M, int N, int K)
{
    __shared__ float As[8][128];
    __shared__ float Bs[8][128];
    const int tid = threadIdx.x;
    const int mtile = blockIdx.x, ntile = blockIdx.y;
    const int arow = tid >> 1, acol = (tid & 1) << 2;
    const int brow = tid >> 5, bcol = (tid & 31) << 2;
    const float* Aptr = A + (size_t)(mtile * 128 + arow) * K + acol;
    const float* Bptr = Bm + (size_t)brow * N + ntile * 128 + bcol;
    const int tr = (tid >> 4) << 3, tc = (tid & 15) << 3;

    float acc[8][8];
#pragma unroll
    for (int i = 0; i < 8; i++)
#pragma unroll
        for (int j = 0; j < 8; j++) acc[i][j] = 0.0f;

    for (int k0 = 0; k0 < K; k0 += 8) {
        float4 av = *(const float4*)(Aptr + k0);
        As[acol + 0][arow] = av.x;
        As[acol + 1][arow] = av.y;
        As[acol + 2][arow] = av.z;
        As[acol + 3][arow] = av.w;
        float4 bv = *(const float4*)(Bptr + (size_t)k0 * N);
        *(float4*)&Bs[brow][bcol] = bv;
        __syncthreads();
#pragma unroll
        for (int k = 0; k < 8; k++) {
            float4 a0 = *(const float4*)&As[k][tr];
            float4 a1 = *(const float4*)&As[k][tr + 4];
            float4 b0 = *(const float4*)&Bs[k][tc];
            float4 b1 = *(const float4*)&Bs[k][tc + 4];
            float a[8] = {a0.x, a0.y, a0.z, a0.w, a1.x, a1.y, a1.z, a1.w};
            float b[8] = {b0.x, b0.y, b0.z, b0.w, b1.x, b1.y, b1.z, b1.w};
#pragma unroll
            for (int i = 0; i < 8; i++)
#pragma unroll
                for (int j = 0; j < 8; j++)
                    acc[i][j] = fmaf(a[i], b[j], acc[i][j]);
        }
        __syncthreads();
    }

#pragma unroll
    for (int i = 0; i < 8; i++) {
        float* Crow = C + (size_t)(mtile * 128 + tr + i) * N + ntile * 128 + tc;
#pragma unroll
        for (int j = 0; j < 8; j++) {
            float vv = acc[i][j];
            if (bias) vv += bias[ntile * 128 + tc + j];
            if (GELU) {
                float t = vv;
                float inner = 0.7978845608028654f * (t + 0.044715f * t * t * t);
                vv = 0.5f * t * (1.0f + tanhf(inner));
            }
            Crow[j] = vv;
        }
    }
}

// ---------------- fused windowed cosine attention ----------------
__global__ void __launch_bounds__(256) attn_kernel(
    const float* __restrict__ q, const float* __restrict__ k, const float* __restrict__ v,
    const float* __restrict__ tau, const float* __restrict__ tbl,
    float* __restrict__ out)
{
    __shared__ float sq[64][33], sk[64][33], sv[64][33];
    __shared__ float sattn[64][65];
    __shared__ float qn[64], kn[64];

    int blk = blockIdx.x;          // bw*16 + head
    int head = blk & 15, bw = blk >> 4;
    int win = bw & 63;
    int tid = threadIdx.x;
    size_t base = (size_t)bw * 64 * C_ + head * HD_;

    for (int i = tid; i < 2048; i += 256) {
        int n = i >> 5, d = i & 31;
        size_t off = base + (size_t)n * C_ + d;
        sq[n][d] = q[off];
        sk[n][d] = k[off];
        sv[n][d] = v[off];
    }
    __syncthreads();

    if (tid < 128) {
        int n = tid & 63;
        float s = 0.0f;
        if (tid < 64) {
            for (int d = 0; d < 32; d++) { float a = sq[n][d]; s = fmaf(a, a, s); }
            qn[n] = sqrtf(s);
        } else {
            for (int d = 0; d < 32; d++) { float a = sk[n][d]; s = fmaf(a, a, s); }
            kn[n] = sqrtf(s);
        }
    }
    __syncthreads();

    float ls = fmaxf(tau[head] + 2.302585092994046f, 0.01f);
    int whb = (win >> 3) << 3, wwb = (win & 7) << 3;

    for (int i = tid; i < 4096; i += 256) {
        int n = i >> 6, m = i & 63;
        float dot = 0.0f;
#pragma unroll
        for (int d = 0; d < 32; d++) dot = fmaf(sq[n][d], sk[m][d], dot);
        float a = dot / fmaxf(qn[n] * kn[m], 1e-6f) * ls;
        // continuous relative position bias
        int dr = (n >> 3) - (m >> 3), dc = (n & 7) - (m & 7);
        float bsv = tbl[((dr + 7) * 15 + (dc + 7)) * 16 + head];
        a += 16.0f / (1.0f + expf(-bsv));
        // shifted-window mask: region comparison in shifted-image coords
        int hn = whb + (n >> 3), wn = wwb + (n & 7);
        int hm = whb + (m >> 3), wm = wwb + (m & 7);
        int rn = (hn < 56 ? 0 : (hn < 60 ? 1 : 2)) * 3 + (wn < 56 ? 0 : (wn < 60 ? 1 : 2));
        int rm = (hm < 56 ? 0 : (hm < 60 ? 1 : 2)) * 3 + (wm < 56 ? 0 : (wm < 60 ? 1 : 2));
        if (rn != rm) a -= 100.0f;
        sattn[n][m] = a;
    }
    __syncthreads();

    {   // softmax: warp per 8 rows, 2 elements per lane
        int warp = tid >> 5, lane = tid & 31;
        for (int r = 0; r < 8; ++r) {
            int n = (warp << 3) + r;
            float a0 = sattn[n][lane], a1 = sattn[n][lane + 32];
            float mx = fmaxf(a0, a1);
#pragma unroll
            for (int o = 16; o; o >>= 1) mx = fmaxf(mx, __shfl_xor_sync(0xffffffffu, mx, o));
            float e0 = expf(a0 - mx), e1 = expf(a1 - mx);
            float s = e0 + e1;
#pragma unroll
            for (int o = 16; o; o >>= 1) s += __shfl_xor_sync(0xffffffffu, s, o);
            float inv = 1.0f / s;
            sattn[n][lane] = e0 * inv;
            sattn[n][lane + 32] = e1 * inv;
        }
    }
    __syncthreads();

    for (int i = tid; i < 2048; i += 256) {
        int n = i >> 5, d = i & 31;
        float o = 0.0f;
#pragma unroll 16
        for (int m = 0; m < 64; m++) o = fmaf(sattn[n][m], sv[m][d], o);
        out[base + (size_t)n * C_ + d] = o;
    }
}

// ---------------- (optional gather) + LayerNorm + residual ----------------
__global__ void __launch_bounds__(128) ln_res_kernel(
    const float* __restrict__ src, const float* __restrict__ resid,
    const float* __restrict__ g, const float* __restrict__ bb,
    float* __restrict__ dst, int gather)
{
    int r = blockIdx.x, tid = threadIdx.x;
    int srow = r;
    if (gather) {   // window reverse + roll(+4,+4)
        int b = r >> 12, hw = r & 4095;
        int h = hw >> 6, w = hw & 63;
        int hh = (h + 60) & 63, wv = (w + 60) & 63;
        srow = (((b << 6) + ((hh >> 3) << 3) + (wv >> 3)) << 6) + ((hh & 7) << 3) + (wv & 7);
    }
    float4 val = ((const float4*)(src + (size_t)srow * C_))[tid];
    __shared__ float sh[4];

    float s = val.x + val.y + val.z + val.w;
#pragma unroll
    for (int o = 16; o; o >>= 1) s += __shfl_xor_sync(0xffffffffu, s, o);
    if ((tid & 31) == 0) sh[tid >> 5] = s;
    __syncthreads();
    float mean = (sh[0] + sh[1] + sh[2] + sh[3]) * (1.0f / 512.0f);
    __syncthreads();

    float dx = val.x - mean, dy = val.y - mean, dz = val.z - mean, dw = val.w - mean;
    float s2 = dx * dx + dy * dy + dz * dz + dw * dw;
#pragma unroll
    for (int o = 16; o; o >>= 1) s2 += __shfl_xor_sync(0xffffffffu, s2, o);
    if ((tid & 31) == 0) sh[tid >> 5] = s2;
    __syncthreads();
    float var = (sh[0] + sh[1] + sh[2] + sh[3]) * (1.0f / 512.0f);
    float rstd = rsqrtf(var + 1e-6f);

    float4 gg = ((const float4*)g)[tid];
    float4 bv = ((const float4*)bb)[tid];
    float4 xr = ((const float4*)(resid + (size_t)r * C_))[tid];
    float4 o;
    o.x = xr.x + dx * rstd * gg.x + bv.x;
    o.y = xr.y + dy * rstd * gg.y + bv.y;
    o.z = xr.z + dz * rstd * gg.z + bv.z;
    o.w = xr.w + dw * rstd * gg.w + bv.w;
    ((float4*)(dst + (size_t)r * C_))[tid] = o;
}

// ---------------- host launch ----------------
extern "C" void kernel_launch(void* const* d_in, const int* in_sizes, int n_in,
                              void* d_out, int out_size)
{
    const float* x      = (const float*)d_in[0];
    const float* q_w    = (const float*)d_in[1];
    const float* q_b    = (const float*)d_in[2];
    const float* k_w    = (const float*)d_in[3];
    const float* v_w    = (const float*)d_in[4];
    const float* v_b    = (const float*)d_in[5];
    const float* proj_w = (const float*)d_in[6];
    const float* proj_b = (const float*)d_in[7];
    const float* tau    = (const float*)d_in[8];
    const float* cpb_w1 = (const float*)d_in[9];
    const float* cpb_b1 = (const float*)d_in[10];
    const float* cpb_w2 = (const float*)d_in[11];
    const float* cpb_b2 = (const float*)d_in[12];
    const float* n1g    = (const float*)d_in[13];
    const float* n1b    = (const float*)d_in[14];
    const float* n2g    = (const float*)d_in[15];
    const float* n2b    = (const float*)d_in[16];
    const float* w1     = (const float*)d_in[17];
    const float* b1     = (const float*)d_in[18];
    const float* w2     = (const float*)d_in[19];
    const float* b2     = (const float*)d_in[20];
    float* out = (float*)d_out;

    float *xw, *q, *k, *v, *hb, *tbl;
    cudaGetSymbolAddress((void**)&xw,  g_xw);
    cudaGetSymbolAddress((void**)&q,   g_q);
    cudaGetSymbolAddress((void**)&k,   g_k);
    cudaGetSymbolAddress((void**)&v,   g_v);
    cudaGetSymbolAddress((void**)&hb,  g_h);
    cudaGetSymbolAddress((void**)&tbl, g_tbl);

    // 1. CPB bias table
    cpb_kernel<<<225, 512>>>(cpb_w1, cpb_b1, cpb_w2, cpb_b2, tbl);
    // 2. shift + window partition
    gather_xw<<<(NROW * 128) / 256, 256>>>(x, xw);
    // 3-5. QKV projections
    dim3 g512(NROW / 128, C_ / 128);
    sgemm_kernel<0><<<g512, 256>>>(xw, q_w, q_b,    q, NROW, C_, C_);
    sgemm_kernel<0><<<g512, 256>>>(xw, k_w, (const float*)nullptr, k, NROW, C_, C_);
    sgemm_kernel<0><<<g512, 256>>>(xw, v_w, v_b,    v, NROW, C_, C_);
    // 6. windowed cosine attention -> xw
    attn_kernel<<<16384, 256>>>(q, k, v, tau, tbl, xw);
    // 7. output projection -> q (y)
    sgemm_kernel<0><<<g512, 256>>>(xw, proj_w, proj_b, q, NROW, C_, C_);
    // 8. window reverse + unshift + LN1 + residual -> v (x1)
    ln_res_kernel<<<NTOK, 128>>>(q, x, n1g, n1b, v, 1);
    // 9. MLP fc1 + gelu -> hb
    dim3 g2048(NROW / 128, 2048 / 128);
    sgemm_kernel<1><<<g2048, 256>>>(v, w1, b1, hb, NROW, 2048, C_);
    // 10. MLP fc2 -> k (h2)
    sgemm_kernel<0><<<g512, 256>>>(hb, w2, b2, k, NROW, C_, 2048);
    // 11. LN2 + residual -> out
    ln_res_kernel<<<NTOK, 128>>>(k, v, n2g, n2b, out, 0);
}

// round 3
// speedup vs baseline: 2.5151x; 2.5151x over previous
#include <cuda_runtime.h>
#include <math.h>
#include <stdint.h>

// Problem constants
#define B_   16
#define H_   64
#define W_   64
#define C_   512
#define NH_  16
#define HD_  32
#define NTOK 65536
#define NWIN 64
#define NROW 65536

// ---------------- device scratch (allocation-free) ----------------
__device__ float g_xw[(size_t)NROW * C_];
__device__ float g_q [(size_t)NROW * C_];
__device__ float g_k [(size_t)NROW * C_];
__device__ float g_v [(size_t)NROW * C_];
__device__ float g_h [(size_t)NROW * 2048];
__device__ float g_tbl[225 * 16];

// ---------------- helpers ----------------
__device__ __forceinline__ uint32_t f2tf32(float x) {
    uint32_t r;
    asm("cvt.rna.tf32.f32 %0, %1;" : "=r"(r) : "f"(x));
    return r;
}
__device__ __forceinline__ void mma_tf32(float* c, uint32_t a0, uint32_t a1,
                                         uint32_t a2, uint32_t a3,
                                         uint32_t b0, uint32_t b1) {
    asm volatile(
        "mma.sync.aligned.m16n8k8.row.col.f32.tf32.tf32.f32 "
        "{%0,%1,%2,%3}, {%4,%5,%6,%7}, {%8,%9}, {%0,%1,%2,%3};"
        : "+f"(c[0]), "+f"(c[1]), "+f"(c[2]), "+f"(c[3])
        : "r"(a0), "r"(a1), "r"(a2), "r"(a3), "r"(b0), "r"(b1));
}
__device__ __forceinline__ float gelu_f(float t) {
    return 0.5f * t * (1.0f + tanhf(0.7978845608028654f * (t + 0.044715f * t * t * t)));
}

// ---------------- tf32 mma.sync GEMM: C[M,N] = A[M,K]*B[K,N] (+bias)(gelu) ----
// CTA 128x128, 8 warps (2x4 -> 64x32 each), K-chunk 32, register-staged loads.
#define A_STRIDE 36      // [m][k] floats, pad 4 -> conflict-free frag LDS
#define B_STRIDE 136     // [k][n] floats, pad 8 -> conflict-free frag LDS
template<int GELU>
__global__ void __launch_bounds__(256) mma_gemm(
    const float* __restrict__ A, const float* __restrict__ B,
    const float* __restrict__ bias, float* __restrict__ C,
    int N, int K)
{
    __shared__ uint32_t As[128 * A_STRIDE];
    __shared__ uint32_t Bs[32 * B_STRIDE];

    const int tid = threadIdx.x;
    const int wid = tid >> 5, lane = tid & 31;
    const int g = lane >> 2, t = lane & 3;
    const int wm = wid >> 2, wn = wid & 3;          // 2 x 4 warp grid
    const int mw = wm * 64, nw = wn * 32;
    const int m0 = blockIdx.y * 128, n0 = blockIdx.x * 128;

    // per-thread staging coordinates
    const int arow = tid >> 3, ac4 = (tid & 7) << 2;       // + r*32 rows
    const int brow = tid >> 5, bc4 = (tid & 31) << 2;      // + r*8  rows

    float acc[4][4][4];
#pragma unroll
    for (int i = 0; i < 4; i++)
#pragma unroll
        for (int j = 0; j < 4; j++)
#pragma unroll
            for (int q = 0; q < 4; q++) acc[i][j][q] = 0.0f;

    const int nch = K >> 5;
    float4 av[4], bv[4];

    // prefetch chunk 0
#pragma unroll
    for (int r = 0; r < 4; ++r) {
        av[r] = *(const float4*)(A + (size_t)(m0 + arow + r * 32) * K + ac4);
        bv[r] = *(const float4*)(B + (size_t)(brow + r * 8) * N + n0 + bc4);
    }

    for (int ch = 0; ch < nch; ++ch) {
        __syncthreads();   // all warps done reading smem from previous chunk
#pragma unroll
        for (int r = 0; r < 4; ++r) {
            uint32_t* ap = &As[(arow + r * 32) * A_STRIDE + ac4];
            ap[0] = f2tf32(av[r].x); ap[1] = f2tf32(av[r].y);
            ap[2] = f2tf32(av[r].z); ap[3] = f2tf32(av[r].w);
            uint32_t* bp = &Bs[(brow + r * 8) * B_STRIDE + bc4];
            bp[0] = f2tf32(bv[r].x); bp[1] = f2tf32(bv[r].y);
            bp[2] = f2tf32(bv[r].z); bp[3] = f2tf32(bv[r].w);
        }
        __syncthreads();

        // prefetch next chunk (overlaps MMA below)
        if (ch + 1 < nch) {
            const int k0 = (ch + 1) << 5;
#pragma unroll
            for (int r = 0; r < 4; ++r) {
                av[r] = *(const float4*)(A + (size_t)(m0 + arow + r * 32) * K + k0 + ac4);
                bv[r] = *(const float4*)(B + (size_t)(k0 + brow + r * 8) * N + n0 + bc4);
            }
        }

#pragma unroll
        for (int ks = 0; ks < 4; ++ks) {
            const int kb = ks << 3;
            uint32_t bf[4][2];
#pragma unroll
            for (int nf = 0; nf < 4; ++nf) {
                const int col = nw + nf * 8 + g;
                bf[nf][0] = Bs[(kb + t) * B_STRIDE + col];
                bf[nf][1] = Bs[(kb + t + 4) * B_STRIDE + col];
            }
#pragma unroll
            for (int mf = 0; mf < 4; ++mf) {
                const int mr = mw + mf * 16 + g;
                uint32_t a0 = As[mr * A_STRIDE + kb + t];
                uint32_t a1 = As[(mr + 8) * A_STRIDE + kb + t];
                uint32_t a2 = As[mr * A_STRIDE + kb + t + 4];
                uint32_t a3 = As[(mr + 8) * A_STRIDE + kb + t + 4];
#pragma unroll
                for (int nf = 0; nf < 4; ++nf)
                    mma_tf32(acc[mf][nf], a0, a1, a2, a3, bf[nf][0], bf[nf][1]);
            }
        }
    }

    // epilogue
#pragma unroll
    for (int mf = 0; mf < 4; ++mf) {
        const int row = m0 + mw + mf * 16 + g;
#pragma unroll
        for (int nf = 0; nf < 4; ++nf) {
            const int col = n0 + nw + nf * 8 + t * 2;
            float b0 = 0.f, b1 = 0.f;
            if (bias) { b0 = bias[col]; b1 = bias[col + 1]; }
            float c0 = acc[mf][nf][0] + b0, c1 = acc[mf][nf][1] + b1;
            float c2 = acc[mf][nf][2] + b0, c3 = acc[mf][nf][3] + b1;
            if (GELU) { c0 = gelu_f(c0); c1 = gelu_f(c1); c2 = gelu_f(c2); c3 = gelu_f(c3); }
            *(float2*)(C + (size_t)row * N + col)       = make_float2(c0, c1);
            *(float2*)(C + (size_t)(row + 8) * N + col) = make_float2(c2, c3);
        }
    }
}

// ---------------- CPB bias table ----------------
__global__ void cpb_kernel(const float* __restrict__ w1, const float* __restrict__ b1,
                           const float* __restrict__ w2, const float* __restrict__ b2,
                           float* __restrict__ tbl)
{
    int f = blockIdx.x;
    int h = threadIdx.x;
    int i = f / 15, j = f % 15;
    float v0 = 8.0f * (float)(j - 7) / 7.0f;
    float v1 = 8.0f * (float)(i - 7) / 7.0f;
    float c0 = copysignf(log2f(fabsf(v0) + 1.0f) * (1.0f / 3.0f), v0);
    float c1 = copysignf(log2f(fabsf(v1) + 1.0f) * (1.0f / 3.0f), v1);
    float hid = fmaxf(c0 * w1[h] + c1 * w1[512 + h] + b1[h], 0.0f);

    __shared__ float red[512];
    for (int nh = 0; nh < 16; ++nh) {
        red[h] = hid * w2[h * 16 + nh];
        __syncthreads();
        for (int s = 256; s > 0; s >>= 1) {
            if (h < s) red[h] += red[h + s];
            __syncthreads();
        }
        if (h == 0) tbl[f * 16 + nh] = red[0] + b2[nh];
        __syncthreads();
    }
}

// ---------------- shift + window partition gather ----------------
__global__ void gather_xw(const float* __restrict__ x, float* __restrict__ xw)
{
    size_t idx = (size_t)blockIdx.x * 256 + threadIdx.x;
    if (idx >= (size_t)NROW * 128) return;
    int c4  = (int)(idx & 127);
    int row = (int)(idx >> 7);
    int n = row & 63, bw = row >> 6;
    int win = bw & 63, b = bw >> 6;
    int wh = win >> 3, wwn = win & 7;
    int i = n >> 3, j = n & 7;
    int h = ((wh << 3) + i + 4) & 63;
    int w = ((wwn << 3) + j + 4) & 63;
    const float4* src = (const float4*)(x + (size_t)((b << 12) + (h << 6) + w) * C_) + c4;
    ((float4*)(xw + (size_t)row * C_))[c4] = *src;
}

// ---------------- fused windowed cosine attention ----------------
__global__ void __launch_bounds__(256) attn_kernel(
    const float* __restrict__ q, const float* __restrict__ k, const float* __restrict__ v,
    const float* __restrict__ tau, const float* __restrict__ tbl,
    float* __restrict__ out)
{
    __shared__ float sq[64][33], sk[64][33], sv[64][33];
    __shared__ float sattn[64][65];
    __shared__ float qn[64], kn[64];

    int blk = blockIdx.x;
    int head = blk & 15, bw = blk >> 4;
    int win = bw & 63;
    int tid = threadIdx.x;
    size_t base = (size_t)bw * 64 * C_ + head * HD_;

    for (int i = tid; i < 2048; i += 256) {
        int n = i >> 5, d = i & 31;
        size_t off = base + (size_t)n * C_ + d;
        sq[n][d] = q[off];
        sk[n][d] = k[off];
        sv[n][d] = v[off];
    }
    __syncthreads();

    if (tid < 128) {
        int n = tid & 63;
        float s = 0.0f;
        if (tid < 64) {
            for (int d = 0; d < 32; d++) { float a = sq[n][d]; s = fmaf(a, a, s); }
            qn[n] = sqrtf(s);
        } else {
            for (int d = 0; d < 32; d++) { float a = sk[n][d]; s = fmaf(a, a, s); }
            kn[n] = sqrtf(s);
        }
    }
    __syncthreads();

    float ls = fmaxf(tau[head] + 2.302585092994046f, 0.01f);
    int whb = (win >> 3) << 3, wwb = (win & 7) << 3;

    for (int i = tid; i < 4096; i += 256) {
        int n = i >> 6, m = i & 63;
        float dot = 0.0f;
#pragma unroll
        for (int d = 0; d < 32; d++) dot = fmaf(sq[n][d], sk[m][d], dot);
        float a = dot / fmaxf(qn[n] * kn[m], 1e-6f) * ls;
        int dr = (n >> 3) - (m >> 3), dc = (n & 7) - (m & 7);
        float bsv = tbl[((dr + 7) * 15 + (dc + 7)) * 16 + head];
        a += 16.0f / (1.0f + expf(-bsv));
        int hn = whb + (n >> 3), wn = wwb + (n & 7);
        int hm = whb + (m >> 3), wm = wwb + (m & 7);
        int rn = (hn < 56 ? 0 : (hn < 60 ? 1 : 2)) * 3 + (wn < 56 ? 0 : (wn < 60 ? 1 : 2));
        int rm = (hm < 56 ? 0 : (hm < 60 ? 1 : 2)) * 3 + (wm < 56 ? 0 : (wm < 60 ? 1 : 2));
        if (rn != rm) a -= 100.0f;
        sattn[n][m] = a;
    }
    __syncthreads();

    {
        int warp = tid >> 5, lane = tid & 31;
        for (int r = 0; r < 8; ++r) {
            int n = (warp << 3) + r;
            float a0 = sattn[n][lane], a1 = sattn[n][lane + 32];
            float mx = fmaxf(a0, a1);
#pragma unroll
            for (int o = 16; o; o >>= 1) mx = fmaxf(mx, __shfl_xor_sync(0xffffffffu, mx, o));
            float e0 = expf(a0 - mx), e1 = expf(a1 - mx);
            float s = e0 + e1;
#pragma unroll
            for (int o = 16; o; o >>= 1) s += __shfl_xor_sync(0xffffffffu, s, o);
            float inv = 1.0f / s;
            sattn[n][lane] = e0 * inv;
            sattn[n][lane + 32] = e1 * inv;
        }
    }
    __syncthreads();

    for (int i = tid; i < 2048; i += 256) {
        int n = i >> 5, d = i & 31;
        float o = 0.0f;
#pragma unroll 16
        for (int m = 0; m < 64; m++) o = fmaf(sattn[n][m], sv[m][d], o);
        out[base + (size_t)n * C_ + d] = o;
    }
}

// ---------------- (optional gather) + LayerNorm + residual ----------------
__global__ void __launch_bounds__(128) ln_res_kernel(
    const float* __restrict__ src, const float* __restrict__ resid,
    const float* __restrict__ g, const float* __restrict__ bb,
    float* __restrict__ dst, int gather)
{
    int r = blockIdx.x, tid = threadIdx.x;
    int srow = r;
    if (gather) {
        int b = r >> 12, hw = r & 4095;
        int h = hw >> 6, w = hw & 63;
        int hh = (h + 60) & 63, wv = (w + 60) & 63;
        srow = (((b << 6) + ((hh >> 3) << 3) + (wv >> 3)) << 6) + ((hh & 7) << 3) + (wv & 7);
    }
    float4 val = ((const float4*)(src + (size_t)srow * C_))[tid];
    __shared__ float sh[4];

    float s = val.x + val.y + val.z + val.w;
#pragma unroll
    for (int o = 16; o; o >>= 1) s += __shfl_xor_sync(0xffffffffu, s, o);
    if ((tid & 31) == 0) sh[tid >> 5] = s;
    __syncthreads();
    float mean = (sh[0] + sh[1] + sh[2] + sh[3]) * (1.0f / 512.0f);
    __syncthreads();

    float dx = val.x - mean, dy = val.y - mean, dz = val.z - mean, dw = val.w - mean;
    float s2 = dx * dx + dy * dy + dz * dz + dw * dw;
#pragma unroll
    for (int o = 16; o; o >>= 1) s2 += __shfl_xor_sync(0xffffffffu, s2, o);
    if ((tid & 31) == 0) sh[tid >> 5] = s2;
    __syncthreads();
    float var = (sh[0] + sh[1] + sh[2] + sh[3]) * (1.0f / 512.0f);
    float rstd = rsqrtf(var + 1e-6f);

    float4 gg = ((const float4*)g)[tid];
    float4 bv = ((const float4*)bb)[tid];
    float4 xr = ((const float4*)(resid + (size_t)r * C_))[tid];
    float4 o;
    o.x = xr.x + dx * rstd * gg.x + bv.x;
    o.y = xr.y + dy * rstd * gg.y + bv.y;
    o.z = xr.z + dz * rstd * gg.z + bv.z;
    o.w = xr.w + dw * rstd * gg.w + bv.w;
    ((float4*)(dst + (size_t)r * C_))[tid] = o;
}

// ---------------- host launch ----------------
extern "C" void kernel_launch(void* const* d_in, const int* in_sizes, int n_in,
                              void* d_out, int out_size)
{
    const float* x      = (const float*)d_in[0];
    const float* q_w    = (const float*)d_in[1];
    const float* q_b    = (const float*)d_in[2];
    const float* k_w    = (const float*)d_in[3];
    const float* v_w    = (const float*)d_in[4];
    const float* v_b    = (const float*)d_in[5];
    const float* proj_w = (const float*)d_in[6];
    const float* proj_b = (const float*)d_in[7];
    const float* tau    = (const float*)d_in[8];
    const float* cpb_w1 = (const float*)d_in[9];
    const float* cpb_b1 = (const float*)d_in[10];
    const float* cpb_w2 = (const float*)d_in[11];
    const float* cpb_b2 = (const float*)d_in[12];
    const float* n1g    = (const float*)d_in[13];
    const float* n1b    = (const float*)d_in[14];
    const float* n2g    = (const float*)d_in[15];
    const float* n2b    = (const float*)d_in[16];
    const float* w1     = (const float*)d_in[17];
    const float* b1     = (const float*)d_in[18];
    const float* w2     = (const float*)d_in[19];
    const float* b2     = (const float*)d_in[20];
    float* out = (float*)d_out;

    float *xw, *q, *k, *v, *hb, *tbl;
    cudaGetSymbolAddress((void**)&xw,  g_xw);
    cudaGetSymbolAddress((void**)&q,   g_q);
    cudaGetSymbolAddress((void**)&k,   g_k);
    cudaGetSymbolAddress((void**)&v,   g_v);
    cudaGetSymbolAddress((void**)&hb,  g_h);
    cudaGetSymbolAddress((void**)&tbl, g_tbl);

    cpb_kernel<<<225, 512>>>(cpb_w1, cpb_b1, cpb_w2, cpb_b2, tbl);
    gather_xw<<<(NROW * 128) / 256, 256>>>(x, xw);

    dim3 gq(4, 512);
    mma_gemm<0><<<gq, 256>>>(xw, q_w, q_b,    q, 512, 512);
    mma_gemm<0><<<gq, 256>>>(xw, k_w, (const float*)nullptr, k, 512, 512);
    mma_gemm<0><<<gq, 256>>>(xw, v_w, v_b,    v, 512, 512);

    attn_kernel<<<16384, 256>>>(q, k, v, tau, tbl, xw);

    mma_gemm<0><<<gq, 256>>>(xw, proj_w, proj_b, q, 512, 512);
    ln_res_kernel<<<NTOK, 128>>>(q, x, n1g, n1b, v, 1);

    mma_gemm<1><<<dim3(16, 512), 256>>>(v, w1, b1, hb, 2048, 512);
    mma_gemm<0><<<gq, 256>>>(hb, w2, b2, k, 512, 2048);
    ln_res_kernel<<<NTOK, 128>>>(k, v, n2g, n2b, out, 0);
}

// round 4
// speedup vs baseline: 2.9179x; 1.1601x over previous
#include <cuda_runtime.h>
#include <math.h>
#include <stdint.h>

// Problem constants
#define B_   16
#define H_   64
#define W_   64
#define C_   512
#define NH_  16
#define HD_  32
#define NTOK 65536
#define NWIN 64
#define NROW 65536

// ---------------- device scratch (allocation-free) ----------------
__device__ float g_xw[(size_t)NROW * C_];    // rounded activations (GEMM A inputs)
__device__ float g_q [(size_t)NROW * C_];
__device__ float g_k [(size_t)NROW * C_];
__device__ float g_v [(size_t)NROW * C_];
__device__ float g_h [(size_t)NROW * 2048];
__device__ float g_wr[3145728];              // tf32-rounded weights
__device__ float g_tbl[225 * 16];

// ---------------- helpers ----------------
__device__ __forceinline__ uint32_t smem_u32(const void* p) {
    uint32_t a;
    asm("{ .reg .u64 t; cvta.to.shared.u64 t, %1; cvt.u32.u64 %0, t; }" : "=r"(a) : "l"(p));
    return a;
}
__device__ __forceinline__ uint32_t f2tf32(float x) {
    uint32_t r;
    asm("cvt.rna.tf32.f32 %0, %1;" : "=r"(r) : "f"(x));
    return r;
}
__device__ __forceinline__ float roundtf(float x) {
    return __uint_as_float(f2tf32(x));
}
__device__ __forceinline__ void cp16(void* sdst, const void* gsrc) {
    uint32_t s = smem_u32(sdst);
    asm volatile("cp.async.cg.shared.global [%0], [%1], 16;" :: "r"(s), "l"(gsrc) : "memory");
}
#define CP_COMMIT() asm volatile("cp.async.commit_group;" ::: "memory")
#define CP_WAIT1()  asm volatile("cp.async.wait_group 1;" ::: "memory")

__device__ __forceinline__ void mma_tf32(float* c, uint32_t a0, uint32_t a1,
                                         uint32_t a2, uint32_t a3,
                                         uint32_t b0, uint32_t b1) {
    asm volatile(
        "mma.sync.aligned.m16n8k8.row.col.f32.tf32.tf32.f32 "
        "{%0,%1,%2,%3}, {%4,%5,%6,%7}, {%8,%9}, {%0,%1,%2,%3};"
        : "+f"(c[0]), "+f"(c[1]), "+f"(c[2]), "+f"(c[3])
        : "r"(a0), "r"(a1), "r"(a2), "r"(a3), "r"(b0), "r"(b1));
}
__device__ __forceinline__ float gelu_f(float t) {
    return 0.5f * t * (1.0f + tanhf(0.7978845608028654f * (t + 0.044715f * t * t * t)));
}

// ---------------- tf32-round copy (weights) ----------------
__global__ void round_kernel(const float* __restrict__ src, float* __restrict__ dst, int n4)
{
    int i = blockIdx.x * 256 + threadIdx.x;
    if (i >= n4) return;
    float4 vv = ((const float4*)src)[i];
    vv.x = roundtf(vv.x); vv.y = roundtf(vv.y);
    vv.z = roundtf(vv.z); vv.w = roundtf(vv.w);
    ((float4*)dst)[i] = vv;
}

// ---------------- tf32 mma.sync GEMM with cp.async double buffer ------------
// C[M,N] = A[M,K]*B[K,N] (+bias)(gelu)(round). A,B pre-rounded to tf32 bits.
// CTA 128x128, 8 warps (2x4 -> 64x32), K-chunk 32, 2 smem stages, 2 CTAs/SM.
#define A_STRIDE 36      // [m][k] floats, pad 4
#define B_STRIDE 136     // [k][n] floats, pad 8
#define SA_F (128 * A_STRIDE)            // 4608 floats
#define SB_F (32 * B_STRIDE)             // 4352 floats
#define STAGE_F (SA_F + SB_F)            // 8960 floats
#define GEMM_SMEM (2 * STAGE_F * 4)      // 71680 bytes

__device__ __forceinline__ void stage_loads(
    float* sm, const float* A, const float* B,
    int m0, int n0, int k0, int N, int K, int tid)
{
    const int arow = tid >> 3, ac4 = (tid & 7) << 2;
    const int brow = tid >> 5, bc4 = (tid & 31) << 2;
    float* as = sm;
    float* bs = sm + SA_F;
#pragma unroll
    for (int r = 0; r < 4; ++r) {
        cp16(&as[(arow + r * 32) * A_STRIDE + ac4],
             A + (size_t)(m0 + arow + r * 32) * K + k0 + ac4);
        cp16(&bs[(brow + r * 8) * B_STRIDE + bc4],
             B + (size_t)(k0 + brow + r * 8) * N + n0 + bc4);
    }
}

template<int GELU, int ROUND_OUT>
__global__ void __launch_bounds__(256, 2) mma_gemm(
    const float* __restrict__ A, const float* __restrict__ B,
    const float* __restrict__ bias, float* __restrict__ C,
    int N, int K)
{
    extern __shared__ float smem[];
    const int tid = threadIdx.x;
    const int wid = tid >> 5, lane = tid & 31;
    const int g = lane >> 2, t = lane & 3;
    const int wm = wid >> 2, wn = wid & 3;
    const int mw = wm * 64, nw = wn * 32;
    const int m0 = blockIdx.y * 128, n0 = blockIdx.x * 128;

    float acc[4][4][4];
#pragma unroll
    for (int i = 0; i < 4; i++)
#pragma unroll
        for (int j = 0; j < 4; j++)
#pragma unroll
            for (int q = 0; q < 4; q++) acc[i][j][q] = 0.0f;

    const int nch = K >> 5;

    stage_loads(smem, A, B, m0, n0, 0, N, K, tid);
    CP_COMMIT();
    stage_loads(smem + STAGE_F, A, B, m0, n0, 32, N, K, tid);
    CP_COMMIT();

    for (int ch = 0; ch < nch; ++ch) {
        CP_WAIT1();
        __syncthreads();
        const int s = ch & 1;
        const uint32_t* As = (const uint32_t*)(smem + s * STAGE_F);
        const uint32_t* Bs = (const uint32_t*)(smem + s * STAGE_F + SA_F);

#pragma unroll
        for (int ks = 0; ks < 4; ++ks) {
            const int kb = ks << 3;
            uint32_t bf[4][2];
#pragma unroll
            for (int nf = 0; nf < 4; ++nf) {
                const int col = nw + nf * 8 + g;
                bf[nf][0] = Bs[(kb + t) * B_STRIDE + col];
                bf[nf][1] = Bs[(kb + t + 4) * B_STRIDE + col];
            }
#pragma unroll
            for (int mf = 0; mf < 4; ++mf) {
                const int mr = mw + mf * 16 + g;
                uint32_t a0 = As[mr * A_STRIDE + kb + t];
                uint32_t a1 = As[(mr + 8) * A_STRIDE + kb + t];
                uint32_t a2 = As[mr * A_STRIDE + kb + t + 4];
                uint32_t a3 = As[(mr + 8) * A_STRIDE + kb + t + 4];
#pragma unroll
                for (int nf = 0; nf < 4; ++nf)
                    mma_tf32(acc[mf][nf], a0, a1, a2, a3, bf[nf][0], bf[nf][1]);
            }
        }
        __syncthreads();
        if (ch + 2 < nch)
            stage_loads(smem + s * STAGE_F, A, B, m0, n0, (ch + 2) << 5, N, K, tid);
        CP_COMMIT();
    }

    // epilogue
#pragma unroll
    for (int mf = 0; mf < 4; ++mf) {
        const int row = m0 + mw + mf * 16 + g;
#pragma unroll
        for (int nf = 0; nf < 4; ++nf) {
            const int col = n0 + nw + nf * 8 + t * 2;
            float b0 = 0.f, b1 = 0.f;
            if (bias) { b0 = bias[col]; b1 = bias[col + 1]; }
            float c0 = acc[mf][nf][0] + b0, c1 = acc[mf][nf][1] + b1;
            float c2 = acc[mf][nf][2] + b0, c3 = acc[mf][nf][3] + b1;
            if (GELU) { c0 = gelu_f(c0); c1 = gelu_f(c1); c2 = gelu_f(c2); c3 = gelu_f(c3); }
            if (ROUND_OUT) {
                c0 = roundtf(c0); c1 = roundtf(c1); c2 = roundtf(c2); c3 = roundtf(c3);
            }
            *(float2*)(C + (size_t)row * N + col)       = make_float2(c0, c1);
            *(float2*)(C + (size_t)(row + 8) * N + col) = make_float2(c2, c3);
        }
    }
}

// ---------------- CPB bias table ----------------
__global__ void cpb_kernel(const float* __restrict__ w1, const float* __restrict__ b1,
                           const float* __restrict__ w2, const float* __restrict__ b2,
                           float* __restrict__ tbl)
{
    int f = blockIdx.x;
    int h = threadIdx.x;
    int i = f / 15, j = f % 15;
    float v0 = 8.0f * (float)(j - 7) / 7.0f;
    float v1 = 8.0f * (float)(i - 7) / 7.0f;
    float c0 = copysignf(log2f(fabsf(v0) + 1.0f) * (1.0f / 3.0f), v0);
    float c1 = copysignf(log2f(fabsf(v1) + 1.0f) * (1.0f / 3.0f), v1);
    float hid = fmaxf(c0 * w1[h] + c1 * w1[512 + h] + b1[h], 0.0f);

    __shared__ float red[512];
    for (int nh = 0; nh < 16; ++nh) {
        red[h] = hid * w2[h * 16 + nh];
        __syncthreads();
        for (int s = 256; s > 0; s >>= 1) {
            if (h < s) red[h] += red[h + s];
            __syncthreads();
        }
        if (h == 0) tbl[f * 16 + nh] = red[0] + b2[nh];
        __syncthreads();
    }
}

// ---------------- shift + window partition gather (rounds to tf32) ----------
__global__ void gather_xw(const float* __restrict__ x, float* __restrict__ xw)
{
    size_t idx = (size_t)blockIdx.x * 256 + threadIdx.x;
    if (idx >= (size_t)NROW * 128) return;
    int c4  = (int)(idx & 127);
    int row = (int)(idx >> 7);
    int n = row & 63, bw = row >> 6;
    int win = bw & 63, b = bw >> 6;
    int wh = win >> 3, wwn = win & 7;
    int i = n >> 3, j = n & 7;
    int h = ((wh << 3) + i + 4) & 63;
    int w = ((wwn << 3) + j + 4) & 63;
    float4 vv = *(((const float4*)(x + (size_t)((b << 12) + (h << 6) + w) * C_)) + c4);
    vv.x = roundtf(vv.x); vv.y = roundtf(vv.y);
    vv.z = roundtf(vv.z); vv.w = roundtf(vv.w);
    ((float4*)(xw + (size_t)row * C_))[c4] = vv;
}

// ---------------- fused windowed cosine attention (rounds output) -----------
__global__ void __launch_bounds__(256) attn_kernel(
    const float* __restrict__ q, const float* __restrict__ k, const float* __restrict__ v,
    const float* __restrict__ tau, const float* __restrict__ tbl,
    float* __restrict__ out)
{
    __shared__ float sq[64][33], sk[64][33], sv[64][33];
    __shared__ float sattn[64][65];
    __shared__ float qn[64], kn[64];

    int blk = blockIdx.x;
    int head = blk & 15, bw = blk >> 4;
    int win = bw & 63;
    int tid = threadIdx.x;
    size_t base = (size_t)bw * 64 * C_ + head * HD_;

    for (int i = tid; i < 2048; i += 256) {
        int n = i >> 5, d = i & 31;
        size_t off = base + (size_t)n * C_ + d;
        sq[n][d] = q[off];
        sk[n][d] = k[off];
        sv[n][d] = v[off];
    }
    __syncthreads();

    if (tid < 128) {
        int n = tid & 63;
        float s = 0.0f;
        if (tid < 64) {
            for (int d = 0; d < 32; d++) { float a = sq[n][d]; s = fmaf(a, a, s); }
            qn[n] = sqrtf(s);
        } else {
            for (int d = 0; d < 32; d++) { float a = sk[n][d]; s = fmaf(a, a, s); }
            kn[n] = sqrtf(s);
        }
    }
    __syncthreads();

    float ls = fmaxf(tau[head] + 2.302585092994046f, 0.01f);
    int whb = (win >> 3) << 3, wwb = (win & 7) << 3;

    for (int i = tid; i < 4096; i += 256) {
        int n = i >> 6, m = i & 63;
        float dot = 0.0f;
#pragma unroll
        for (int d = 0; d < 32; d++) dot = fmaf(sq[n][d], sk[m][d], dot);
        float a = dot / fmaxf(qn[n] * kn[m], 1e-6f) * ls;
        int dr = (n >> 3) - (m >> 3), dc = (n & 7) - (m & 7);
        float bsv = tbl[((dr + 7) * 15 + (dc + 7)) * 16 + head];
        a += 16.0f / (1.0f + expf(-bsv));
        int hn = whb + (n >> 3), wn = wwb + (n & 7);
        int hm = whb + (m >> 3), wm = wwb + (m & 7);
        int rn = (hn < 56 ? 0 : (hn < 60 ? 1 : 2)) * 3 + (wn < 56 ? 0 : (wn < 60 ? 1 : 2));
        int rm = (hm < 56 ? 0 : (hm < 60 ? 1 : 2)) * 3 + (wm < 56 ? 0 : (wm < 60 ? 1 : 2));
        if (rn != rm) a -= 100.0f;
        sattn[n][m] = a;
    }
    __syncthreads();

    {
        int warp = tid >> 5, lane = tid & 31;
        for (int r = 0; r < 8; ++r) {
            int n = (warp << 3) + r;
            float a0 = sattn[n][lane], a1 = sattn[n][lane + 32];
            float mx = fmaxf(a0, a1);
#pragma unroll
            for (int o = 16; o; o >>= 1) mx = fmaxf(mx, __shfl_xor_sync(0xffffffffu, mx, o));
            float e0 = expf(a0 - mx), e1 = expf(a1 - mx);
            float s = e0 + e1;
#pragma unroll
            for (int o = 16; o; o >>= 1) s += __shfl_xor_sync(0xffffffffu, s, o);
            float inv = 1.0f / s;
            sattn[n][lane] = e0 * inv;
            sattn[n][lane + 32] = e1 * inv;
        }
    }
    __syncthreads();

    for (int i = tid; i < 2048; i += 256) {
        int n = i >> 5, d = i & 31;
        float o = 0.0f;
#pragma unroll 16
        for (int m = 0; m < 64; m++) o = fmaf(sattn[n][m], sv[m][d], o);
        out[base + (size_t)n * C_ + d] = roundtf(o);   // feeds proj GEMM only
    }
}

// ---------------- (optional gather) + LayerNorm + residual ----------------
__global__ void __launch_bounds__(128) ln_res_kernel(
    const float* __restrict__ src, const float* __restrict__ resid,
    const float* __restrict__ g, const float* __restrict__ bb,
    float* __restrict__ dst, float* __restrict__ dst_rounded, int gather)
{
    int r = blockIdx.x, tid = threadIdx.x;
    int srow = r;
    if (gather) {
        int b = r >> 12, hw = r & 4095;
        int h = hw >> 6, w = hw & 63;
        int hh = (h + 60) & 63, wv = (w + 60) & 63;
        srow = (((b << 6) + ((hh >> 3) << 3) + (wv >> 3)) << 6) + ((hh & 7) << 3) + (wv & 7);
    }
    float4 val = ((const float4*)(src + (size_t)srow * C_))[tid];
    __shared__ float sh[4];

    float s = val.x + val.y + val.z + val.w;
#pragma unroll
    for (int o = 16; o; o >>= 1) s += __shfl_xor_sync(0xffffffffu, s, o);
    if ((tid & 31) == 0) sh[tid >> 5] = s;
    __syncthreads();
    float mean = (sh[0] + sh[1] + sh[2] + sh[3]) * (1.0f / 512.0f);
    __syncthreads();

    float dx = val.x - mean, dy = val.y - mean, dz = val.z - mean, dw = val.w - mean;
    float s2 = dx * dx + dy * dy + dz * dz + dw * dw;
#pragma unroll
    for (int o = 16; o; o >>= 1) s2 += __shfl_xor_sync(0xffffffffu, s2, o);
    if ((tid & 31) == 0) sh[tid >> 5] = s2;
    __syncthreads();
    float var = (sh[0] + sh[1] + sh[2] + sh[3]) * (1.0f / 512.0f);
    float rstd = rsqrtf(var + 1e-6f);

    float4 gg = ((const float4*)g)[tid];
    float4 bv = ((const float4*)bb)[tid];
    float4 xr = ((const float4*)(resid + (size_t)r * C_))[tid];
    float4 o;
    o.x = xr.x + dx * rstd * gg.x + bv.x;
    o.y = xr.y + dy * rstd * gg.y + bv.y;
    o.z = xr.z + dz * rstd * gg.z + bv.z;
    o.w = xr.w + dw * rstd * gg.w + bv.w;
    ((float4*)(dst + (size_t)r * C_))[tid] = o;
    if (dst_rounded) {
        float4 ro;
        ro.x = roundtf(o.x); ro.y = roundtf(o.y);
        ro.z = roundtf(o.z); ro.w = roundtf(o.w);
        ((float4*)(dst_rounded + (size_t)r * C_))[tid] = ro;
    }
}

// ---------------- host launch ----------------
extern "C" void kernel_launch(void* const* d_in, const int* in_sizes, int n_in,
                              void* d_out, int out_size)
{
    const float* x      = (const float*)d_in[0];
    const float* q_w    = (const float*)d_in[1];
    const float* q_b    = (const float*)d_in[2];
    const float* k_w    = (const float*)d_in[3];
    const float* v_w    = (const float*)d_in[4];
    const float* v_b    = (const float*)d_in[5];
    const float* proj_w = (const float*)d_in[6];
    const float* proj_b = (const float*)d_in[7];
    const float* tau    = (const float*)d_in[8];
    const float* cpb_w1 = (const float*)d_in[9];
    const float* cpb_b1 = (const float*)d_in[10];
    const float* cpb_w2 = (const float*)d_in[11];
    const float* cpb_b2 = (const float*)d_in[12];
    const float* n1g    = (const float*)d_in[13];
    const float* n1b    = (const float*)d_in[14];
    const float* n2g    = (const float*)d_in[15];
    const float* n2b    = (const float*)d_in[16];
    const float* w1     = (const float*)d_in[17];
    const float* b1     = (const float*)d_in[18];
    const float* w2     = (const float*)d_in[19];
    const float* b2     = (const float*)d_in[20];
    float* out = (float*)d_out;

    float *xw, *q, *k, *v, *hb, *wr, *tbl;
    cudaGetSymbolAddress((void**)&xw,  g_xw);
    cudaGetSymbolAddress((void**)&q,   g_q);
    cudaGetSymbolAddress((void**)&k,   g_k);
    cudaGetSymbolAddress((void**)&v,   g_v);
    cudaGetSymbolAddress((void**)&hb,  g_h);
    cudaGetSymbolAddress((void**)&wr,  g_wr);
    cudaGetSymbolAddress((void**)&tbl, g_tbl);

    float* wq = wr;                 // 512x512
    float* wk = wr + 262144;
    float* wv = wr + 524288;
    float* wp = wr + 786432;
    float* wf1 = wr + 1048576;      // 512x2048
    float* wf2 = wr + 2097152;      // 2048x512

    cudaFuncSetAttribute((const void*)mma_gemm<0, 0>,
                         cudaFuncAttributeMaxDynamicSharedMemorySize, GEMM_SMEM);
    cudaFuncSetAttribute((const void*)mma_gemm<1, 1>,
                         cudaFuncAttributeMaxDynamicSharedMemorySize, GEMM_SMEM);

    round_kernel<<<256, 256>>>(q_w,    wq, 65536);
    round_kernel<<<256, 256>>>(k_w,    wk, 65536);
    round_kernel<<<256, 256>>>(v_w,    wv, 65536);
    round_kernel<<<256, 256>>>(proj_w, wp, 65536);
    round_kernel<<<1024, 256>>>(w1,    wf1, 262144);
    round_kernel<<<1024, 256>>>(w2,    wf2, 262144);

    cpb_kernel<<<225, 512>>>(cpb_w1, cpb_b1, cpb_w2, cpb_b2, tbl);
    gather_xw<<<(NROW * 128) / 256, 256>>>(x, xw);

    dim3 gq(4, 512);
    mma_gemm<0, 0><<<gq, 256, GEMM_SMEM>>>(xw, wq, q_b, q, 512, 512);
    mma_gemm<0, 0><<<gq, 256, GEMM_SMEM>>>(xw, wk, (const float*)nullptr, k, 512, 512);
    mma_gemm<0, 0><<<gq, 256, GEMM_SMEM>>>(xw, wv, v_b, v, 512, 512);

    attn_kernel<<<16384, 256>>>(q, k, v, tau, tbl, xw);

    mma_gemm<0, 0><<<gq, 256, GEMM_SMEM>>>(xw, wp, proj_b, q, 512, 512);
    // x1 fp32 -> v (residual use), rounded copy -> xw (fc1 input)
    ln_res_kernel<<<NTOK, 128>>>(q, x, n1g, n1b, v, xw, 1);

    mma_gemm<1, 1><<<dim3(16, 512), 256, GEMM_SMEM>>>(xw, wf1, b1, hb, 2048, 512);
    mma_gemm<0, 0><<<gq, 256, GEMM_SMEM>>>(hb, wf2, b2, k, 512, 2048);
    ln_res_kernel<<<NTOK, 128>>>(k, v, n2g, n2b, out, (float*)nullptr, 0);
}

// round 5
// speedup vs baseline: 4.2887x; 1.4698x over previous
#include <cuda_runtime.h>
#include <cuda_fp16.h>
#include <math.h>
#include <stdint.h>

// Problem constants
#define B_   16
#define H_   64
#define W_   64
#define C_   512
#define NH_  16
#define HD_  32
#define NTOK 65536
#define NWIN 64
#define NROW 65536

// ---------------- device scratch (allocation-free) ----------------
__device__ float g_xw[(size_t)NROW * C_];    // half activations (u32-packed), reused
__device__ float g_q [(size_t)NROW * C_];    // fp32 q / proj-out / fc2-out
__device__ float g_k [(size_t)NROW * C_];    // fp32 k
__device__ float g_v [(size_t)NROW * C_];    // fp32 v / x1
__device__ float g_h [(size_t)NROW * 2048];  // half hb (uses half the space)
__device__ float g_wr[3145728];              // packed half weights (u32 view)
__device__ float g_tbl[225 * 16];

// ---------------- helpers ----------------
__device__ __forceinline__ uint32_t smem_u32(const void* p) {
    uint32_t a;
    asm("{ .reg .u64 t; cvta.to.shared.u64 t, %1; cvt.u32.u64 %0, t; }" : "=r"(a) : "l"(p));
    return a;
}
__device__ __forceinline__ uint32_t packh2(float lo, float hi) {
    __half2 h = __floats2half2_rn(lo, hi);
    return *reinterpret_cast<uint32_t*>(&h);
}
__device__ __forceinline__ void cp16(void* sdst, const void* gsrc) {
    uint32_t s = smem_u32(sdst);
    asm volatile("cp.async.cg.shared.global [%0], [%1], 16;" :: "r"(s), "l"(gsrc) : "memory");
}
#define CP_COMMIT() asm volatile("cp.async.commit_group;" ::: "memory")
#define CP_WAIT2()  asm volatile("cp.async.wait_group 2;" ::: "memory")

__device__ __forceinline__ void mma_f16(float* c, uint32_t a0, uint32_t a1,
                                        uint32_t a2, uint32_t a3,
                                        uint32_t b0, uint32_t b1) {
    asm volatile(
        "mma.sync.aligned.m16n8k16.row.col.f32.f16.f16.f32 "
        "{%0,%1,%2,%3}, {%4,%5,%6,%7}, {%8,%9}, {%0,%1,%2,%3};"
        : "+f"(c[0]), "+f"(c[1]), "+f"(c[2]), "+f"(c[3])
        : "r"(a0), "r"(a1), "r"(a2), "r"(a3), "r"(b0), "r"(b1));
}
__device__ __forceinline__ float gelu_f(float t) {
    return 0.5f * t * (1.0f + tanhf(0.7978845608028654f * (t + 0.044715f * t * t * t)));
}

// ---------------- weight convert+pack: src[K][N] f32 -> dst[K/2][N] half2 ----
__global__ void pack_w(const float* __restrict__ src, uint32_t* __restrict__ dst,
                       int N, int K)
{
    int idx = blockIdx.x * 256 + threadIdx.x;       // over uint4 elements
    int n4c = N >> 2;
    int total = (K >> 1) * n4c;
    if (idx >= total) return;
    int n4 = idx % n4c, kp = idx / n4c;
    float4 r0 = ((const float4*)(src + (size_t)(2 * kp) * N))[n4];
    float4 r1 = ((const float4*)(src + (size_t)(2 * kp + 1) * N))[n4];
    uint4 u;
    u.x = packh2(r0.x, r1.x);
    u.y = packh2(r0.y, r1.y);
    u.z = packh2(r0.z, r1.z);
    u.w = packh2(r0.w, r1.w);
    ((uint4*)dst)[idx] = u;
}

// ---------------- fp16 mma.sync GEMM -----------------------------------------
// C[M,N] = A[M,K]*B[K,N] (+bias)(gelu). A: half [M][K]; B: packed [K/2][N] half2.
// CTA 128x128, 8 warps (2x4 -> 64x32), K-chunk 32 halves, 4 cp.async stages.
#define AS_U 20                       // u32 per A smem row (16 data + 4 pad)
#define BS_U 136                      // u32 per B smem row (128 data + 8 pad)
#define SA_U (128 * AS_U)             // 2560
#define SB_U (16 * BS_U)              // 2176
#define STG_U (SA_U + SB_U)           // 4736 u32 = 18944 B
#define GEMM_SMEM (4 * STG_U * 4)     // 75776 B

__device__ __forceinline__ void stage_ab(uint32_t* sm,
    const uint32_t* A, const uint32_t* B,
    int m0, int n0, int ch, int N, int K2, int tid)
{
    uint32_t* as = sm;
    uint32_t* bs = sm + SA_U;
    const int kp0 = ch << 4;
#pragma unroll
    for (int r = 0; r < 2; ++r) {
        int o = tid + (r << 8);
        int row = o >> 2, seg = (o & 3) << 2;
        cp16(&as[row * AS_U + seg], A + (size_t)(m0 + row) * K2 + kp0 + seg);
        int kp = o >> 5, sg = (o & 31) << 2;
        cp16(&bs[kp * BS_U + sg], B + (size_t)(kp0 + kp) * N + n0 + sg);
    }
}

template<int GELU, int HALF_OUT>
__global__ void __launch_bounds__(256, 2) mma_gemm(
    const uint32_t* __restrict__ A, const uint32_t* __restrict__ B,
    const float* __restrict__ bias, void* __restrict__ Cv,
    int N, int K)
{
    extern __shared__ uint32_t smem[];
    const int tid = threadIdx.x;
    const int wid = tid >> 5, lane = tid & 31;
    const int g = lane >> 2, t = lane & 3;
    const int wm = wid >> 2, wn = wid & 3;
    const int mw = wm * 64, nw = wn * 32;
    const int m0 = blockIdx.y * 128, n0 = blockIdx.x * 128;
    const int K2 = K >> 1;

    float acc[4][4][4];
#pragma unroll
    for (int i = 0; i < 4; i++)
#pragma unroll
        for (int j = 0; j < 4; j++)
#pragma unroll
            for (int q = 0; q < 4; q++) acc[i][j][q] = 0.0f;

    const int nch = K >> 5;

#pragma unroll
    for (int s = 0; s < 3; ++s) {
        stage_ab(smem + s * STG_U, A, B, m0, n0, s, N, K2, tid);
        CP_COMMIT();
    }

    for (int ch = 0; ch < nch; ++ch) {
        CP_WAIT2();
        __syncthreads();     // stage ch ready for all; all warps done with ch-1
        // prefetch chunk ch+3 into buffer (ch+3)&3 == (ch-1)&3 (free now)
        if (ch + 3 < nch)
            stage_ab(smem + ((ch + 3) & 3) * STG_U, A, B, m0, n0, ch + 3, N, K2, tid);
        CP_COMMIT();

        const uint32_t* As = smem + (ch & 3) * STG_U;
        const uint32_t* Bs = As + SA_U;
#pragma unroll
        for (int ks = 0; ks < 2; ++ks) {
            const int kb = ks << 3;
            uint32_t bf[4][2];
#pragma unroll
            for (int nf = 0; nf < 4; ++nf) {
                const int col = nw + nf * 8 + g;
                bf[nf][0] = Bs[(kb + t) * BS_U + col];
                bf[nf][1] = Bs[(kb + t + 4) * BS_U + col];
            }
#pragma unroll
            for (int mf = 0; mf < 4; ++mf) {
                const int mr = mw + mf * 16 + g;
                uint32_t a0 = As[mr * AS_U + kb + t];
                uint32_t a1 = As[(mr + 8) * AS_U + kb + t];
                uint32_t a2 = As[mr * AS_U + kb + t + 4];
                uint32_t a3 = As[(mr + 8) * AS_U + kb + t + 4];
#pragma unroll
                for (int nf = 0; nf < 4; ++nf)
                    mma_f16(acc[mf][nf], a0, a1, a2, a3, bf[nf][0], bf[nf][1]);
            }
        }
    }

    // epilogue
#pragma unroll
    for (int mf = 0; mf < 4; ++mf) {
        const int row = m0 + mw + mf * 16 + g;
#pragma unroll
        for (int nf = 0; nf < 4; ++nf) {
            const int col = n0 + nw + nf * 8 + t * 2;
            float b0 = 0.f, b1 = 0.f;
            if (bias) { b0 = bias[col]; b1 = bias[col + 1]; }
            float c0 = acc[mf][nf][0] + b0, c1 = acc[mf][nf][1] + b1;
            float c2 = acc[mf][nf][2] + b0, c3 = acc[mf][nf][3] + b1;
            if (GELU) { c0 = gelu_f(c0); c1 = gelu_f(c1); c2 = gelu_f(c2); c3 = gelu_f(c3); }
            if (HALF_OUT) {
                uint32_t* Ch = (uint32_t*)Cv;   // half2-packed rows, N halves
                Ch[((size_t)row * N + col) >> 1]       = packh2(c0, c1);
                Ch[((size_t)(row + 8) * N + col) >> 1] = packh2(c2, c3);
            } else {
                float* Cf = (float*)Cv;
                *(float2*)(Cf + (size_t)row * N + col)       = make_float2(c0, c1);
                *(float2*)(Cf + (size_t)(row + 8) * N + col) = make_float2(c2, c3);
            }
        }
    }
}

// ---------------- CPB bias table ----------------
__global__ void cpb_kernel(const float* __restrict__ w1, const float* __restrict__ b1,
                           const float* __restrict__ w2, const float* __restrict__ b2,
                           float* __restrict__ tbl)
{
    int f = blockIdx.x;
    int h = threadIdx.x;
    int i = f / 15, j = f % 15;
    float v0 = 8.0f * (float)(j - 7) / 7.0f;
    float v1 = 8.0f * (float)(i - 7) / 7.0f;
    float c0 = copysignf(log2f(fabsf(v0) + 1.0f) * (1.0f / 3.0f), v0);
    float c1 = copysignf(log2f(fabsf(v1) + 1.0f) * (1.0f / 3.0f), v1);
    float hid = fmaxf(c0 * w1[h] + c1 * w1[512 + h] + b1[h], 0.0f);

    __shared__ float red[512];
    for (int nh = 0; nh < 16; ++nh) {
        red[h] = hid * w2[h * 16 + nh];
        __syncthreads();
        for (int s = 256; s > 0; s >>= 1) {
            if (h < s) red[h] += red[h + s];
            __syncthreads();
        }
        if (h == 0) tbl[f * 16 + nh] = red[0] + b2[nh];
        __syncthreads();
    }
}

// ---------------- shift + window partition gather -> half -------------------
__global__ void gather_xw(const float* __restrict__ x, uint32_t* __restrict__ xw)
{
    size_t idx = (size_t)blockIdx.x * 256 + threadIdx.x;   // over float4s
    if (idx >= (size_t)NROW * 128) return;
    int c4  = (int)(idx & 127);
    int row = (int)(idx >> 7);
    int n = row & 63, bw = row >> 6;
    int win = bw & 63, b = bw >> 6;
    int wh = win >> 3, wwn = win & 7;
    int i = n >> 3, j = n & 7;
    int h = ((wh << 3) + i + 4) & 63;
    int w = ((wwn << 3) + j + 4) & 63;
    float4 vv = *(((const float4*)(x + (size_t)((b << 12) + (h << 6) + w) * C_)) + c4);
    uint2 u;
    u.x = packh2(vv.x, vv.y);
    u.y = packh2(vv.z, vv.w);
    *(uint2*)(xw + (size_t)row * 256 + c4 * 2) = u;
}

// ---------------- fused windowed cosine attention (half out) ----------------
__global__ void __launch_bounds__(256) attn_kernel(
    const float* __restrict__ q, const float* __restrict__ k, const float* __restrict__ v,
    const float* __restrict__ tau, const float* __restrict__ tbl,
    __half* __restrict__ out)
{
    __shared__ float sq[64][33], sk[64][33], sv[64][33];
    __shared__ float sattn[64][65];
    __shared__ float qn[64], kn[64];

    int blk = blockIdx.x;
    int head = blk & 15, bw = blk >> 4;
    int win = bw & 63;
    int tid = threadIdx.x;
    size_t base = (size_t)bw * 64 * C_ + head * HD_;

    for (int i = tid; i < 2048; i += 256) {
        int n = i >> 5, d = i & 31;
        size_t off = base + (size_t)n * C_ + d;
        sq[n][d] = q[off];
        sk[n][d] = k[off];
        sv[n][d] = v[off];
    }
    __syncthreads();

    if (tid < 128) {
        int n = tid & 63;
        float s = 0.0f;
        if (tid < 64) {
            for (int d = 0; d < 32; d++) { float a = sq[n][d]; s = fmaf(a, a, s); }
            qn[n] = sqrtf(s);
        } else {
            for (int d = 0; d < 32; d++) { float a = sk[n][d]; s = fmaf(a, a, s); }
            kn[n] = sqrtf(s);
        }
    }
    __syncthreads();

    float ls = fmaxf(tau[head] + 2.302585092994046f, 0.01f);
    int whb = (win >> 3) << 3, wwb = (win & 7) << 3;

    for (int i = tid; i < 4096; i += 256) {
        int n = i >> 6, m = i & 63;
        float dot = 0.0f;
#pragma unroll
        for (int d = 0; d < 32; d++) dot = fmaf(sq[n][d], sk[m][d], dot);
        float a = dot / fmaxf(qn[n] * kn[m], 1e-6f) * ls;
        int dr = (n >> 3) - (m >> 3), dc = (n & 7) - (m & 7);
        float bsv = tbl[((dr + 7) * 15 + (dc + 7)) * 16 + head];
        a += 16.0f / (1.0f + expf(-bsv));
        int hn = whb + (n >> 3), wn = wwb + (n & 7);
        int hm = whb + (m >> 3), wm = wwb + (m & 7);
        int rn = (hn < 56 ? 0 : (hn < 60 ? 1 : 2)) * 3 + (wn < 56 ? 0 : (wn < 60 ? 1 : 2));
        int rm = (hm < 56 ? 0 : (hm < 60 ? 1 : 2)) * 3 + (wm < 56 ? 0 : (wm < 60 ? 1 : 2));
        if (rn != rm) a -= 100.0f;
        sattn[n][m] = a;
    }
    __syncthreads();

    {
        int warp = tid >> 5, lane = tid & 31;
        for (int r = 0; r < 8; ++r) {
            int n = (warp << 3) + r;
            float a0 = sattn[n][lane], a1 = sattn[n][lane + 32];
            float mx = fmaxf(a0, a1);
#pragma unroll
            for (int o = 16; o; o >>= 1) mx = fmaxf(mx, __shfl_xor_sync(0xffffffffu, mx, o));
            float e0 = expf(a0 - mx), e1 = expf(a1 - mx);
            float s = e0 + e1;
#pragma unroll
            for (int o = 16; o; o >>= 1) s += __shfl_xor_sync(0xffffffffu, s, o);
            float inv = 1.0f / s;
            sattn[n][lane] = e0 * inv;
            sattn[n][lane + 32] = e1 * inv;
        }
    }
    __syncthreads();

    for (int i = tid; i < 1024; i += 256) {
        int n = i >> 4, dp = (i & 15) << 1;
        float o0 = 0.0f, o1 = 0.0f;
#pragma unroll 16
        for (int m = 0; m < 64; m++) {
            float p = sattn[n][m];
            o0 = fmaf(p, sv[m][dp], o0);
            o1 = fmaf(p, sv[m][dp + 1], o1);
        }
        *(uint32_t*)(out + (size_t)(bw * 64 + n) * C_ + head * HD_ + dp) = packh2(o0, o1);
    }
}

// ---------------- (optional gather) + LayerNorm + residual ----------------
__global__ void __launch_bounds__(128) ln_res_kernel(
    const float* __restrict__ src, const float* __restrict__ resid,
    const float* __restrict__ g, const float* __restrict__ bb,
    float* __restrict__ dst, uint32_t* __restrict__ dst_half, int gather)
{
    int r = blockIdx.x, tid = threadIdx.x;
    int srow = r;
    if (gather) {
        int b = r >> 12, hw = r & 4095;
        int h = hw >> 6, w = hw & 63;
        int hh = (h + 60) & 63, wv = (w + 60) & 63;
        srow = (((b << 6) + ((hh >> 3) << 3) + (wv >> 3)) << 6) + ((hh & 7) << 3) + (wv & 7);
    }
    float4 val = ((const float4*)(src + (size_t)srow * C_))[tid];
    __shared__ float sh[4];

    float s = val.x + val.y + val.z + val.w;
#pragma unroll
    for (int o = 16; o; o >>= 1) s += __shfl_xor_sync(0xffffffffu, s, o);
    if ((tid & 31) == 0) sh[tid >> 5] = s;
    __syncthreads();
    float mean = (sh[0] + sh[1] + sh[2] + sh[3]) * (1.0f / 512.0f);
    __syncthreads();

    float dx = val.x - mean, dy = val.y - mean, dz = val.z - mean, dw = val.w - mean;
    float s2 = dx * dx + dy * dy + dz * dz + dw * dw;
#pragma unroll
    for (int o = 16; o; o >>= 1) s2 += __shfl_xor_sync(0xffffffffu, s2, o);
    if ((tid & 31) == 0) sh[tid >> 5] = s2;
    __syncthreads();
    float var = (sh[0] + sh[1] + sh[2] + sh[3]) * (1.0f / 512.0f);
    float rstd = rsqrtf(var + 1e-6f);

    float4 gg = ((const float4*)g)[tid];
    float4 bv = ((const float4*)bb)[tid];
    float4 xr = ((const float4*)(resid + (size_t)r * C_))[tid];
    float4 o;
    o.x = xr.x + dx * rstd * gg.x + bv.x;
    o.y = xr.y + dy * rstd * gg.y + bv.y;
    o.z = xr.z + dz * rstd * gg.z + bv.z;
    o.w = xr.w + dw * rstd * gg.w + bv.w;
    ((float4*)(dst + (size_t)r * C_))[tid] = o;
    if (dst_half) {
        uint2 u;
        u.x = packh2(o.x, o.y);
        u.y = packh2(o.z, o.w);
        *(uint2*)(dst_half + (size_t)r * 256 + tid * 2) = u;
    }
}

// ---------------- host launch ----------------
extern "C" void kernel_launch(void* const* d_in, const int* in_sizes, int n_in,
                              void* d_out, int out_size)
{
    const float* x      = (const float*)d_in[0];
    const float* q_w    = (const float*)d_in[1];
    const float* q_b    = (const float*)d_in[2];
    const float* k_w    = (const float*)d_in[3];
    const float* v_w    = (const float*)d_in[4];
    const float* v_b    = (const float*)d_in[5];
    const float* proj_w = (const float*)d_in[6];
    const float* proj_b = (const float*)d_in[7];
    const float* tau    = (const float*)d_in[8];
    const float* cpb_w1 = (const float*)d_in[9];
    const float* cpb_b1 = (const float*)d_in[10];
    const float* cpb_w2 = (const float*)d_in[11];
    const float* cpb_b2 = (const float*)d_in[12];
    const float* n1g    = (const float*)d_in[13];
    const float* n1b    = (const float*)d_in[14];
    const float* n2g    = (const float*)d_in[15];
    const float* n2b    = (const float*)d_in[16];
    const float* w1     = (const float*)d_in[17];
    const float* b1     = (const float*)d_in[18];
    const float* w2     = (const float*)d_in[19];
    const float* b2     = (const float*)d_in[20];
    float* out = (float*)d_out;

    float *xwf, *q, *k, *v, *hbf, *wrf, *tbl;
    cudaGetSymbolAddress((void**)&xwf, g_xw);
    cudaGetSymbolAddress((void**)&q,   g_q);
    cudaGetSymbolAddress((void**)&k,   g_k);
    cudaGetSymbolAddress((void**)&v,   g_v);
    cudaGetSymbolAddress((void**)&hbf, g_h);
    cudaGetSymbolAddress((void**)&wrf, g_wr);
    cudaGetSymbolAddress((void**)&tbl, g_tbl);

    uint32_t* xw = (uint32_t*)xwf;       // half activations
    uint32_t* hb = (uint32_t*)hbf;       // half mlp hidden
    uint32_t* wr = (uint32_t*)wrf;

    uint32_t* wq  = wr;                  // 512x512 packed: 131072 u32 each
    uint32_t* wk  = wr + 131072;
    uint32_t* wv  = wr + 262144;
    uint32_t* wp  = wr + 393216;
    uint32_t* wf1 = wr + 524288;         // [256][2048] u32
    uint32_t* wf2 = wr + 1048576;        // [1024][512] u32

    cudaFuncSetAttribute((const void*)mma_gemm<0, 0>,
                         cudaFuncAttributeMaxDynamicSharedMemorySize, GEMM_SMEM);
    cudaFuncSetAttribute((const void*)mma_gemm<1, 1>,
                         cudaFuncAttributeMaxDynamicSharedMemorySize, GEMM_SMEM);

    pack_w<<<128, 256>>>(q_w,    wq,  512, 512);
    pack_w<<<128, 256>>>(k_w,    wk,  512, 512);
    pack_w<<<128, 256>>>(v_w,    wv,  512, 512);
    pack_w<<<128, 256>>>(proj_w, wp,  512, 512);
    pack_w<<<512, 256>>>(w1,     wf1, 2048, 512);
    pack_w<<<512, 256>>>(w2,     wf2, 512, 2048);

    cpb_kernel<<<225, 512>>>(cpb_w1, cpb_b1, cpb_w2, cpb_b2, tbl);
    gather_xw<<<(NROW * 128) / 256, 256>>>(x, xw);

    dim3 gq(4, 512);
    mma_gemm<0, 0><<<gq, 256, GEMM_SMEM>>>(xw, wq, q_b, q, 512, 512);
    mma_gemm<0, 0><<<gq, 256, GEMM_SMEM>>>(xw, wk, (const float*)nullptr, k, 512, 512);
    mma_gemm<0, 0><<<gq, 256, GEMM_SMEM>>>(xw, wv, v_b, v, 512, 512);

    attn_kernel<<<16384, 256>>>(q, k, v, tau, tbl, (__half*)xw);

    mma_gemm<0, 0><<<gq, 256, GEMM_SMEM>>>(xw, wp, proj_b, q, 512, 512);
    // x1 fp32 -> v (residual), half copy -> xw (fc1 input)
    ln_res_kernel<<<NTOK, 128>>>(q, x, n1g, n1b, v, xw, 1);

    mma_gemm<1, 1><<<dim3(16, 512), 256, GEMM_SMEM>>>(xw, wf1, b1, hb, 2048, 512);
    mma_gemm<0, 0><<<gq, 256, GEMM_SMEM>>>(hb, wf2, b2, q, 512, 2048);
    ln_res_kernel<<<NTOK, 128>>>(q, v, n2g, n2b, out, (uint32_t*)nullptr, 0);
}

// round 6
// speedup vs baseline: 5.5247x; 1.2882x over previous
#include <cuda_runtime.h>
#include <cuda_fp16.h>
#include <math.h>
#include <stdint.h>

// Problem constants
#define B_   16
#define H_   64
#define W_   64
#define C_   512
#define NH_  16
#define HD_  32
#define NTOK 65536
#define NWIN 64
#define NROW 65536

// ---------------- device scratch (allocation-free) ----------------
__device__ float g_xw[(size_t)NROW * C_];    // half activations (u32-packed), reused
__device__ float g_q [(size_t)NROW * C_];    // fp32 proj-out / fc2-out
__device__ float g_v [(size_t)NROW * C_];    // fp32 x1
__device__ float g_h [(size_t)NROW * 2048];  // qkv half (front) + mlp hidden half
__device__ float g_wr[3145728];              // packed half weights (u32 view)
__device__ float g_tbl[225 * 16];
__device__ float g_qkvb[1536];

// ---------------- helpers ----------------
__device__ __forceinline__ uint32_t smem_u32(const void* p) {
    uint32_t a;
    asm("{ .reg .u64 t; cvta.to.shared.u64 t, %1; cvt.u32.u64 %0, t; }" : "=r"(a) : "l"(p));
    return a;
}
__device__ __forceinline__ uint32_t packh2(float lo, float hi) {
    __half2 h = __floats2half2_rn(lo, hi);
    return *reinterpret_cast<uint32_t*>(&h);
}
__device__ __forceinline__ void cp16(void* sdst, const void* gsrc) {
    uint32_t s = smem_u32(sdst);
    asm volatile("cp.async.cg.shared.global [%0], [%1], 16;" :: "r"(s), "l"(gsrc) : "memory");
}
#define CP_COMMIT() asm volatile("cp.async.commit_group;" ::: "memory")
#define CP_WAIT2()  asm volatile("cp.async.wait_group 2;" ::: "memory")

__device__ __forceinline__ void mma_f16(float* c, uint32_t a0, uint32_t a1,
                                        uint32_t a2, uint32_t a3,
                                        uint32_t b0, uint32_t b1) {
    asm volatile(
        "mma.sync.aligned.m16n8k16.row.col.f32.f16.f16.f32 "
        "{%0,%1,%2,%3}, {%4,%5,%6,%7}, {%8,%9}, {%0,%1,%2,%3};"
        : "+f"(c[0]), "+f"(c[1]), "+f"(c[2]), "+f"(c[3])
        : "r"(a0), "r"(a1), "r"(a2), "r"(a3), "r"(b0), "r"(b1));
}
__device__ __forceinline__ float gelu_f(float t) {
    return 0.5f * t * (1.0f + tanhf(0.7978845608028654f * (t + 0.044715f * t * t * t)));
}

// ---------------- weight convert+pack: src[K][N] f32 -> dst[K/2][dstN]+off ---
__global__ void pack_w(const float* __restrict__ src, uint32_t* __restrict__ dst,
                       int N, int K, int dstN, int coloff)
{
    int idx = blockIdx.x * 256 + threadIdx.x;
    int n4c = N >> 2;
    int total = (K >> 1) * n4c;
    if (idx >= total) return;
    int n4 = idx % n4c, kp = idx / n4c;
    float4 r0 = ((const float4*)(src + (size_t)(2 * kp) * N))[n4];
    float4 r1 = ((const float4*)(src + (size_t)(2 * kp + 1) * N))[n4];
    uint4 u;
    u.x = packh2(r0.x, r1.x);
    u.y = packh2(r0.y, r1.y);
    u.z = packh2(r0.z, r1.z);
    u.w = packh2(r0.w, r1.w);
    ((uint4*)(dst + (size_t)kp * dstN + coloff))[n4] = u;
}

__global__ void fuse_bias(const float* __restrict__ qb, const float* __restrict__ vb,
                          float* __restrict__ dst)
{
    int i = blockIdx.x * 256 + threadIdx.x;
    if (i >= 1536) return;
    float v = 0.0f;
    if (i < 512) v = qb[i];
    else if (i >= 1024) v = vb[i - 1024];
    dst[i] = v;
}

// ---------------- fp16 mma.sync GEMM -----------------------------------------
#define AS_U 20
#define BS_U 136
#define SA_U (128 * AS_U)
#define SB_U (16 * BS_U)
#define STG_U (SA_U + SB_U)
#define GEMM_SMEM (4 * STG_U * 4)

__device__ __forceinline__ void stage_ab(uint32_t* sm,
    const uint32_t* A, const uint32_t* B,
    int m0, int n0, int ch, int N, int K2, int tid)
{
    uint32_t* as = sm;
    uint32_t* bs = sm + SA_U;
    const int kp0 = ch << 4;
#pragma unroll
    for (int r = 0; r < 2; ++r) {
        int o = tid + (r << 8);
        int row = o >> 2, seg = (o & 3) << 2;
        cp16(&as[row * AS_U + seg], A + (size_t)(m0 + row) * K2 + kp0 + seg);
        int kp = o >> 5, sg = (o & 31) << 2;
        cp16(&bs[kp * BS_U + sg], B + (size_t)(kp0 + kp) * N + n0 + sg);
    }
}

template<int GELU, int HALF_OUT>
__global__ void __launch_bounds__(256, 2) mma_gemm(
    const uint32_t* __restrict__ A, const uint32_t* __restrict__ B,
    const float* __restrict__ bias, void* __restrict__ Cv,
    int N, int K)
{
    extern __shared__ uint32_t smem[];
    const int tid = threadIdx.x;
    const int wid = tid >> 5, lane = tid & 31;
    const int g = lane >> 2, t = lane & 3;
    const int wm = wid >> 2, wn = wid & 3;
    const int mw = wm * 64, nw = wn * 32;
    const int m0 = blockIdx.y * 128, n0 = blockIdx.x * 128;
    const int K2 = K >> 1;

    float acc[4][4][4];
#pragma unroll
    for (int i = 0; i < 4; i++)
#pragma unroll
        for (int j = 0; j < 4; j++)
#pragma unroll
            for (int q = 0; q < 4; q++) acc[i][j][q] = 0.0f;

    const int nch = K >> 5;

#pragma unroll
    for (int s = 0; s < 3; ++s) {
        stage_ab(smem + s * STG_U, A, B, m0, n0, s, N, K2, tid);
        CP_COMMIT();
    }

    for (int ch = 0; ch < nch; ++ch) {
        CP_WAIT2();
        __syncthreads();
        if (ch + 3 < nch)
            stage_ab(smem + ((ch + 3) & 3) * STG_U, A, B, m0, n0, ch + 3, N, K2, tid);
        CP_COMMIT();

        const uint32_t* As = smem + (ch & 3) * STG_U;
        const uint32_t* Bs = As + SA_U;
#pragma unroll
        for (int ks = 0; ks < 2; ++ks) {
            const int kb = ks << 3;
            uint32_t bf[4][2];
#pragma unroll
            for (int nf = 0; nf < 4; ++nf) {
                const int col = nw + nf * 8 + g;
                bf[nf][0] = Bs[(kb + t) * BS_U + col];
                bf[nf][1] = Bs[(kb + t + 4) * BS_U + col];
            }
#pragma unroll
            for (int mf = 0; mf < 4; ++mf) {
                const int mr = mw + mf * 16 + g;
                uint32_t a0 = As[mr * AS_U + kb + t];
                uint32_t a1 = As[(mr + 8) * AS_U + kb + t];
                uint32_t a2 = As[mr * AS_U + kb + t + 4];
                uint32_t a3 = As[(mr + 8) * AS_U + kb + t + 4];
#pragma unroll
                for (int nf = 0; nf < 4; ++nf)
                    mma_f16(acc[mf][nf], a0, a1, a2, a3, bf[nf][0], bf[nf][1]);
            }
        }
    }

#pragma unroll
    for (int mf = 0; mf < 4; ++mf) {
        const int row = m0 + mw + mf * 16 + g;
#pragma unroll
        for (int nf = 0; nf < 4; ++nf) {
            const int col = n0 + nw + nf * 8 + t * 2;
            float b0 = 0.f, b1 = 0.f;
            if (bias) { b0 = bias[col]; b1 = bias[col + 1]; }
            float c0 = acc[mf][nf][0] + b0, c1 = acc[mf][nf][1] + b1;
            float c2 = acc[mf][nf][2] + b0, c3 = acc[mf][nf][3] + b1;
            if (GELU) { c0 = gelu_f(c0); c1 = gelu_f(c1); c2 = gelu_f(c2); c3 = gelu_f(c3); }
            if (HALF_OUT) {
                uint32_t* Ch = (uint32_t*)Cv;
                Ch[((size_t)row * N + col) >> 1]       = packh2(c0, c1);
                Ch[((size_t)(row + 8) * N + col) >> 1] = packh2(c2, c3);
            } else {
                float* Cf = (float*)Cv;
                *(float2*)(Cf + (size_t)row * N + col)       = make_float2(c0, c1);
                *(float2*)(Cf + (size_t)(row + 8) * N + col) = make_float2(c2, c3);
            }
        }
    }
}

// ---------------- CPB bias table ----------------
__global__ void cpb_kernel(const float* __restrict__ w1, const float* __restrict__ b1,
                           const float* __restrict__ w2, const float* __restrict__ b2,
                           float* __restrict__ tbl)
{
    int f = blockIdx.x;
    int h = threadIdx.x;
    int i = f / 15, j = f % 15;
    float v0 = 8.0f * (float)(j - 7) / 7.0f;
    float v1 = 8.0f * (float)(i - 7) / 7.0f;
    float c0 = copysignf(log2f(fabsf(v0) + 1.0f) * (1.0f / 3.0f), v0);
    float c1 = copysignf(log2f(fabsf(v1) + 1.0f) * (1.0f / 3.0f), v1);
    float hid = fmaxf(c0 * w1[h] + c1 * w1[512 + h] + b1[h], 0.0f);

    __shared__ float red[512];
    for (int nh = 0; nh < 16; ++nh) {
        red[h] = hid * w2[h * 16 + nh];
        __syncthreads();
        for (int s = 256; s > 0; s >>= 1) {
            if (h < s) red[h] += red[h + s];
            __syncthreads();
        }
        if (h == 0) tbl[f * 16 + nh] = red[0] + b2[nh];
        __syncthreads();
    }
}

// ---------------- shift + window partition gather -> half -------------------
__global__ void gather_xw(const float* __restrict__ x, uint32_t* __restrict__ xw)
{
    size_t idx = (size_t)blockIdx.x * 256 + threadIdx.x;
    if (idx >= (size_t)NROW * 128) return;
    int c4  = (int)(idx & 127);
    int row = (int)(idx >> 7);
    int n = row & 63, bw = row >> 6;
    int win = bw & 63, b = bw >> 6;
    int wh = win >> 3, wwn = win & 7;
    int i = n >> 3, j = n & 7;
    int h = ((wh << 3) + i + 4) & 63;
    int w = ((wwn << 3) + j + 4) & 63;
    float4 vv = *(((const float4*)(x + (size_t)((b << 12) + (h << 6) + w) * C_)) + c4);
    uint2 u;
    u.x = packh2(vv.x, vv.y);
    u.y = packh2(vv.z, vv.w);
    *(uint2*)(xw + (size_t)row * 256 + c4 * 2) = u;
}

// ---------------- tensor-core windowed cosine attention ---------------------
// One block per (window, head): 128 threads (4 warps), warp w owns rows 16w..16w+15.
// qkv: u32 view [row][768] (1536 halves: q 0-255, k 256-511, v 512-767 u32)
__global__ void __launch_bounds__(128) attn_tc(
    const uint32_t* __restrict__ qkv,
    const float* __restrict__ tau, const float* __restrict__ tbl,
    uint32_t* __restrict__ out)
{
    __shared__ uint32_t Qh[64 * 17];
    __shared__ uint32_t Kh[64 * 17];
    __shared__ __half sVt[32 * 72];      // V transposed [d][token], stride 72 halves
    __shared__ float qn[64], kn[64];

    const int blk = blockIdx.x;
    const int head = blk & 15, bw = blk >> 4;
    const int win = bw & 63;
    const int tid = threadIdx.x;
    const int wid = tid >> 5, lane = tid & 31;
    const int g = lane >> 2, t = lane & 3;
    const int mr = wid << 4;

    const uint32_t* base = qkv + (size_t)(bw << 6) * 768 + (head << 4);

    // stage Q, K (u32 pair layout = native fragment layout)
    for (int i = tid; i < 1024; i += 128) {
        int tok = i >> 4, c = i & 15;
        Qh[tok * 17 + c] = base[(size_t)tok * 768 + c];
        Kh[tok * 17 + c] = base[(size_t)tok * 768 + 256 + c];
    }
    // stage V transposed
    for (int i = tid; i < 1024; i += 128) {
        int tok = i >> 4, dp = i & 15;
        uint32_t u = base[(size_t)tok * 768 + 512 + dp];
        __half2 h = *(__half2*)&u;
        sVt[(dp * 2) * 72 + tok]     = __low2half(h);
        sVt[(dp * 2 + 1) * 72 + tok] = __high2half(h);
    }
    __syncthreads();

    // norms (fp32 accumulation over 32 halves)
    {
        int tok = tid & 63;
        const uint32_t* src = (tid < 64) ? &Qh[tok * 17] : &Kh[tok * 17];
        float s = 0.0f;
#pragma unroll
        for (int c = 0; c < 16; ++c) {
            float2 f = __half22float2(*(__half2*)&src[c]);
            s = fmaf(f.x, f.x, fmaf(f.y, f.y, s));
        }
        if (tid < 64) qn[tok] = sqrtf(s); else kn[tok] = sqrtf(s);
    }
    __syncthreads();

    // S = Q K^T  (per warp: 16 rows x 64 cols)
    float sacc[8][4];
#pragma unroll
    for (int nf = 0; nf < 8; ++nf)
#pragma unroll
        for (int e = 0; e < 4; ++e) sacc[nf][e] = 0.0f;

    uint32_t aq[2][4];
#pragma unroll
    for (int kb = 0; kb < 2; ++kb) {
        aq[kb][0] = Qh[(mr + g) * 17 + kb * 8 + t];
        aq[kb][1] = Qh[(mr + g + 8) * 17 + kb * 8 + t];
        aq[kb][2] = Qh[(mr + g) * 17 + kb * 8 + t + 4];
        aq[kb][3] = Qh[(mr + g + 8) * 17 + kb * 8 + t + 4];
    }
#pragma unroll
    for (int nf = 0; nf < 8; ++nf) {
        const int col = (nf << 3) + g;
#pragma unroll
        for (int kb = 0; kb < 2; ++kb) {
            uint32_t b0 = Kh[col * 17 + kb * 8 + t];
            uint32_t b1 = Kh[col * 17 + kb * 8 + t + 4];
            mma_f16(sacc[nf], aq[kb][0], aq[kb][1], aq[kb][2], aq[kb][3], b0, b1);
        }
    }

    // fixup: cosine scale + CPB bias + shift mask
    const float ls = fmaxf(tau[head] + 2.302585092994046f, 0.01f);
    const int whb = (win >> 3) << 3, wwb = (win & 7) << 3;
    const int r1 = mr + g, r2 = mr + g + 8;
    float mx1 = -1e30f, mx2 = -1e30f;
#pragma unroll
    for (int nf = 0; nf < 8; ++nf) {
#pragma unroll
        for (int e = 0; e < 4; ++e) {
            const int r = (e < 2) ? r1 : r2;
            const int c = (nf << 3) + (t << 1) + (e & 1);
            float a = sacc[nf][e] / fmaxf(qn[r] * kn[c], 1e-6f) * ls;
            int dr = (r >> 3) - (c >> 3), dc = (r & 7) - (c & 7);
            float bsv = tbl[((dr + 7) * 15 + (dc + 7)) * 16 + head];
            a += 16.0f / (1.0f + expf(-bsv));
            int hn = whb + (r >> 3), wn = wwb + (r & 7);
            int hm = whb + (c >> 3), wm = wwb + (c & 7);
            int rn = (hn < 56 ? 0 : (hn < 60 ? 1 : 2)) * 3 + (wn < 56 ? 0 : (wn < 60 ? 1 : 2));
            int rm = (hm < 56 ? 0 : (hm < 60 ? 1 : 2)) * 3 + (wm < 56 ? 0 : (wm < 60 ? 1 : 2));
            if (rn != rm) a -= 100.0f;
            sacc[nf][e] = a;
            if (e < 2) mx1 = fmaxf(mx1, a); else mx2 = fmaxf(mx2, a);
        }
    }
    // quad-reduce row max (lanes g*4+t share a row)
#pragma unroll
    for (int o = 1; o <= 2; o <<= 1) {
        mx1 = fmaxf(mx1, __shfl_xor_sync(0xffffffffu, mx1, o));
        mx2 = fmaxf(mx2, __shfl_xor_sync(0xffffffffu, mx2, o));
    }
    float s1 = 0.0f, s2 = 0.0f;
#pragma unroll
    for (int nf = 0; nf < 8; ++nf) {
        float e0 = expf(sacc[nf][0] - mx1);
        float e1 = expf(sacc[nf][1] - mx1);
        float e2 = expf(sacc[nf][2] - mx2);
        float e3 = expf(sacc[nf][3] - mx2);
        sacc[nf][0] = e0; sacc[nf][1] = e1; sacc[nf][2] = e2; sacc[nf][3] = e3;
        s1 += e0 + e1; s2 += e2 + e3;
    }
#pragma unroll
    for (int o = 1; o <= 2; o <<= 1) {
        s1 += __shfl_xor_sync(0xffffffffu, s1, o);
        s2 += __shfl_xor_sync(0xffffffffu, s2, o);
    }
    const float inv1 = 1.0f / s1, inv2 = 1.0f / s2;

    // O = P V : S-acc fragments reinterpret directly as PV A-fragments
    float oacc[4][4];
#pragma unroll
    for (int nf = 0; nf < 4; ++nf)
#pragma unroll
        for (int e = 0; e < 4; ++e) oacc[nf][e] = 0.0f;

    const uint32_t* vt32 = (const uint32_t*)sVt;   // [d][36] u32
#pragma unroll
    for (int kc = 0; kc < 4; ++kc) {
        uint32_t a0 = packh2(sacc[kc * 2][0],     sacc[kc * 2][1]);
        uint32_t a1 = packh2(sacc[kc * 2][2],     sacc[kc * 2][3]);
        uint32_t a2 = packh2(sacc[kc * 2 + 1][0], sacc[kc * 2 + 1][1]);
        uint32_t a3 = packh2(sacc[kc * 2 + 1][2], sacc[kc * 2 + 1][3]);
#pragma unroll
        for (int nf = 0; nf < 4; ++nf) {
            const int d = (nf << 3) + g;
            uint32_t b0 = vt32[d * 36 + kc * 8 + t];
            uint32_t b1 = vt32[d * 36 + kc * 8 + t + 4];
            mma_f16(oacc[nf], a0, a1, a2, a3, b0, b1);
        }
    }

    // write half output (scale by 1/rowsum)
    const size_t orow1 = (size_t)((bw << 6) + r1) * 256 + (head << 4);
    const size_t orow2 = (size_t)((bw << 6) + r2) * 256 + (head << 4);
#pragma unroll
    for (int nf = 0; nf < 4; ++nf) {
        out[orow1 + (nf << 2) + t] = packh2(oacc[nf][0] * inv1, oacc[nf][1] * inv1);
        out[orow2 + (nf << 2) + t] = packh2(oacc[nf][2] * inv2, oacc[nf][3] * inv2);
    }
}

// ---------------- (optional gather) + LayerNorm + residual ----------------
__global__ void __launch_bounds__(128) ln_res_kernel(
    const float* __restrict__ src, const float* __restrict__ resid,
    const float* __restrict__ g, const float* __restrict__ bb,
    float* __restrict__ dst, uint32_t* __restrict__ dst_half, int gather)
{
    int r = blockIdx.x, tid = threadIdx.x;
    int srow = r;
    if (gather) {
        int b = r >> 12, hw = r & 4095;
        int h = hw >> 6, w = hw & 63;
        int hh = (h + 60) & 63, wv = (w + 60) & 63;
        srow = (((b << 6) + ((hh >> 3) << 3) + (wv >> 3)) << 6) + ((hh & 7) << 3) + (wv & 7);
    }
    float4 val = ((const float4*)(src + (size_t)srow * C_))[tid];
    __shared__ float sh[4];

    float s = val.x + val.y + val.z + val.w;
#pragma unroll
    for (int o = 16; o; o >>= 1) s += __shfl_xor_sync(0xffffffffu, s, o);
    if ((tid & 31) == 0) sh[tid >> 5] = s;
    __syncthreads();
    float mean = (sh[0] + sh[1] + sh[2] + sh[3]) * (1.0f / 512.0f);
    __syncthreads();

    float dx = val.x - mean, dy = val.y - mean, dz = val.z - mean, dw = val.w - mean;
    float s2 = dx * dx + dy * dy + dz * dz + dw * dw;
#pragma unroll
    for (int o = 16; o; o >>= 1) s2 += __shfl_xor_sync(0xffffffffu, s2, o);
    if ((tid & 31) == 0) sh[tid >> 5] = s2;
    __syncthreads();
    float var = (sh[0] + sh[1] + sh[2] + sh[3]) * (1.0f / 512.0f);
    float rstd = rsqrtf(var + 1e-6f);

    float4 gg = ((const float4*)g)[tid];
    float4 bv = ((const float4*)bb)[tid];
    float4 xr = ((const float4*)(resid + (size_t)r * C_))[tid];
    float4 o;
    o.x = xr.x + dx * rstd * gg.x + bv.x;
    o.y = xr.y + dy * rstd * gg.y + bv.y;
    o.z = xr.z + dz * rstd * gg.z + bv.z;
    o.w = xr.w + dw * rstd * gg.w + bv.w;
    ((float4*)(dst + (size_t)r * C_))[tid] = o;
    if (dst_half) {
        uint2 u;
        u.x = packh2(o.x, o.y);
        u.y = packh2(o.z, o.w);
        *(uint2*)(dst_half + (size_t)r * 256 + tid * 2) = u;
    }
}

// ---------------- host launch ----------------
extern "C" void kernel_launch(void* const* d_in, const int* in_sizes, int n_in,
                              void* d_out, int out_size)
{
    const float* x      = (const float*)d_in[0];
    const float* q_w    = (const float*)d_in[1];
    const float* q_b    = (const float*)d_in[2];
    const float* k_w    = (const float*)d_in[3];
    const float* v_w    = (const float*)d_in[4];
    const float* v_b    = (const float*)d_in[5];
    const float* proj_w = (const float*)d_in[6];
    const float* proj_b = (const float*)d_in[7];
    const float* tau    = (const float*)d_in[8];
    const float* cpb_w1 = (const float*)d_in[9];
    const float* cpb_b1 = (const float*)d_in[10];
    const float* cpb_w2 = (const float*)d_in[11];
    const float* cpb_b2 = (const float*)d_in[12];
    const float* n1g    = (const float*)d_in[13];
    const float* n1b    = (const float*)d_in[14];
    const float* n2g    = (const float*)d_in[15];
    const float* n2b    = (const float*)d_in[16];
    const float* w1     = (const float*)d_in[17];
    const float* b1     = (const float*)d_in[18];
    const float* w2     = (const float*)d_in[19];
    const float* b2     = (const float*)d_in[20];
    float* out = (float*)d_out;

    float *xwf, *q, *v, *hf, *wrf, *tbl, *qkvb;
    cudaGetSymbolAddress((void**)&xwf,  g_xw);
    cudaGetSymbolAddress((void**)&q,    g_q);
    cudaGetSymbolAddress((void**)&v,    g_v);
    cudaGetSymbolAddress((void**)&hf,   g_h);
    cudaGetSymbolAddress((void**)&wrf,  g_wr);
    cudaGetSymbolAddress((void**)&tbl,  g_tbl);
    cudaGetSymbolAddress((void**)&qkvb, g_qkvb);

    uint32_t* xw   = (uint32_t*)xwf;                  // half activations
    uint32_t* qkvh = (uint32_t*)hf;                   // half qkv [row][1536]
    uint32_t* hb   = (uint32_t*)(hf + 50331648);      // half mlp hidden [row][2048]
    uint32_t* wr   = (uint32_t*)wrf;

    uint32_t* wqkv = wr;                 // [256][1536] u32
    uint32_t* wp   = wr + 393216;        // [256][512]
    uint32_t* wf1  = wr + 524288;        // [256][2048]
    uint32_t* wf2  = wr + 1048576;       // [1024][512]

    cudaFuncSetAttribute((const void*)mma_gemm<0, 0>,
                         cudaFuncAttributeMaxDynamicSharedMemorySize, GEMM_SMEM);
    cudaFuncSetAttribute((const void*)mma_gemm<0, 1>,
                         cudaFuncAttributeMaxDynamicSharedMemorySize, GEMM_SMEM);
    cudaFuncSetAttribute((const void*)mma_gemm<1, 1>,
                         cudaFuncAttributeMaxDynamicSharedMemorySize, GEMM_SMEM);

    pack_w<<<128, 256>>>(q_w,    wqkv, 512, 512, 1536, 0);
    pack_w<<<128, 256>>>(k_w,    wqkv, 512, 512, 1536, 512);
    pack_w<<<128, 256>>>(v_w,    wqkv, 512, 512, 1536, 1024);
    pack_w<<<128, 256>>>(proj_w, wp,   512, 512, 512, 0);
    pack_w<<<512, 256>>>(w1,     wf1,  2048, 512, 2048, 0);
    pack_w<<<512, 256>>>(w2,     wf2,  512, 2048, 512, 0);
    fuse_bias<<<6, 256>>>(q_b, v_b, qkvb);

    cpb_kernel<<<225, 512>>>(cpb_w1, cpb_b1, cpb_w2, cpb_b2, tbl);
    gather_xw<<<(NROW * 128) / 256, 256>>>(x, xw);

    // fused QKV: [65536 x 1536] half
    mma_gemm<0, 1><<<dim3(12, 512), 256, GEMM_SMEM>>>(xw, wqkv, qkvb, qkvh, 1536, 512);

    // tensor-core attention -> xw (half)
    attn_tc<<<16384, 128>>>(qkvh, tau, tbl, xw);

    mma_gemm<0, 0><<<dim3(4, 512), 256, GEMM_SMEM>>>(xw, wp, proj_b, q, 512, 512);
    ln_res_kernel<<<NTOK, 128>>>(q, x, n1g, n1b, v, xw, 1);

    mma_gemm<1, 1><<<dim3(16, 512), 256, GEMM_SMEM>>>(xw, wf1, b1, hb, 2048, 512);
    mma_gemm<0, 0><<<dim3(4, 512), 256, GEMM_SMEM>>>(hb, wf2, b2, q, 512, 2048);
    ln_res_kernel<<<NTOK, 128>>>(q, v, n2g, n2b, out, (uint32_t*)nullptr, 0);
}

// round 7
// speedup vs baseline: 5.6979x; 1.0314x over previous
#include <cuda_runtime.h>
#include <cuda_fp16.h>
#include <math.h>
#include <stdint.h>

// Problem constants
#define B_   16
#define H_   64
#define W_   64
#define C_   512
#define NH_  16
#define HD_  32
#define NTOK 65536
#define NWIN 64
#define NROW 65536

// ---------------- device scratch (allocation-free) ----------------
__device__ float g_xw[(size_t)NROW * C_];    // half activations (u32-packed), reused
__device__ float g_q [(size_t)NROW * C_];    // fp32 proj-out / fc2-out
__device__ float g_v [(size_t)NROW * C_];    // fp32 x1
__device__ float g_h [(size_t)NROW * 2048];  // qkv half (front) + mlp hidden half
__device__ float g_wr[3145728];              // plain-half weights (u32 view)
__device__ float g_tbl[225 * 16];
__device__ float g_qkvb[1536];

// ---------------- helpers ----------------
__device__ __forceinline__ uint32_t smem_u32(const void* p) {
    uint32_t a;
    asm("{ .reg .u64 t; cvta.to.shared.u64 t, %1; cvt.u32.u64 %0, t; }" : "=r"(a) : "l"(p));
    return a;
}
__device__ __forceinline__ uint32_t packh2(float lo, float hi) {
    __half2 h = __floats2half2_rn(lo, hi);
    return *reinterpret_cast<uint32_t*>(&h);
}
__device__ __forceinline__ void cp16(void* sdst, const void* gsrc) {
    uint32_t s = smem_u32(sdst);
    asm volatile("cp.async.cg.shared.global [%0], [%1], 16;" :: "r"(s), "l"(gsrc) : "memory");
}
#define CP_COMMIT() asm volatile("cp.async.commit_group;" ::: "memory")
#define CP_WAIT2()  asm volatile("cp.async.wait_group 2;" ::: "memory")

__device__ __forceinline__ void ldsm4(const void* p, uint32_t* r) {
    uint32_t a = smem_u32(p);
    asm volatile("ldmatrix.sync.aligned.m8n8.x4.shared.b16 {%0,%1,%2,%3}, [%4];"
        : "=r"(r[0]), "=r"(r[1]), "=r"(r[2]), "=r"(r[3]) : "r"(a));
}
__device__ __forceinline__ void ldsm4t(const void* p, uint32_t* r) {
    uint32_t a = smem_u32(p);
    asm volatile("ldmatrix.sync.aligned.m8n8.x4.trans.shared.b16 {%0,%1,%2,%3}, [%4];"
        : "=r"(r[0]), "=r"(r[1]), "=r"(r[2]), "=r"(r[3]) : "r"(a));
}
__device__ __forceinline__ void mma_f16(float* c, uint32_t a0, uint32_t a1,
                                        uint32_t a2, uint32_t a3,
                                        uint32_t b0, uint32_t b1) {
    asm volatile(
        "mma.sync.aligned.m16n8k16.row.col.f32.f16.f16.f32 "
        "{%0,%1,%2,%3}, {%4,%5,%6,%7}, {%8,%9}, {%0,%1,%2,%3};"
        : "+f"(c[0]), "+f"(c[1]), "+f"(c[2]), "+f"(c[3])
        : "r"(a0), "r"(a1), "r"(a2), "r"(a3), "r"(b0), "r"(b1));
}
__device__ __forceinline__ float gelu_f(float t) {
    return 0.5f * t * (1.0f + tanhf(0.7978845608028654f * (t + 0.044715f * t * t * t)));
}

// ---------------- merged prep: all weights f32 -> plain half, + fused bias ---
// dst half layout [K][N] row-major (u32 view [K][N/2]).
__device__ __forceinline__ void pack_one(const float* __restrict__ src, uint32_t* __restrict__ dst,
                                         int N, int dstN2, int coloff, int local)
{
    int n8c = N >> 3;
    int k = local / n8c, n8 = local % n8c;
    const float4* s = (const float4*)(src + (size_t)k * N + (n8 << 3));
    float4 f0 = s[0], f1 = s[1];
    uint4 u;
    u.x = packh2(f0.x, f0.y);
    u.y = packh2(f0.z, f0.w);
    u.z = packh2(f1.x, f1.y);
    u.w = packh2(f1.z, f1.w);
    *(uint4*)(dst + (size_t)k * dstN2 + coloff + (n8 << 2)) = u;
}

__global__ void pack_all(const float* __restrict__ q_w, const float* __restrict__ k_w,
                         const float* __restrict__ v_w, const float* __restrict__ p_w,
                         const float* __restrict__ w1, const float* __restrict__ w2,
                         const float* __restrict__ qb, const float* __restrict__ vb,
                         uint32_t* __restrict__ wqkv, uint32_t* __restrict__ wp,
                         uint32_t* __restrict__ wf1, uint32_t* __restrict__ wf2,
                         float* __restrict__ qkvb)
{
    int idx = blockIdx.x * 256 + threadIdx.x;
    if (idx < 32768)        pack_one(q_w, wqkv, 512, 768, 0,   idx);
    else if (idx < 65536)   pack_one(k_w, wqkv, 512, 768, 256, idx - 32768);
    else if (idx < 98304)   pack_one(v_w, wqkv, 512, 768, 512, idx - 65536);
    else if (idx < 131072)  pack_one(p_w, wp,   512, 256, 0,   idx - 98304);
    else if (idx < 262144)  pack_one(w1,  wf1, 2048, 1024, 0,  idx - 131072);
    else if (idx < 393216)  pack_one(w2,  wf2,  512, 256, 0,   idx - 262144);
    else if (idx < 394752) {
        int i = idx - 393216;
        float v = 0.0f;
        if (i < 512) v = qb[i];
        else if (i >= 1024) v = vb[i - 1024];
        qkvb[i] = v;
    }
}

// ---------------- fp16 mma.sync GEMM with ldmatrix ---------------------------
// C[M,N] = A[M,K]*B[K,N] (+bias)(gelu). A: half [M][K]; B: plain half [K][N].
// CTA 128x128, 8 warps (2x4 -> 64x32), K-chunk 32, 4 cp.async stages.
#define AS_U 20                       // u32 per A smem row (16 data + 4 pad)
#define BS_U 68                       // u32 per B smem k-row (64 data + 4 pad)
#define SA_U (128 * AS_U)             // 2560
#define SB_U (32 * BS_U)              // 2176
#define STG_U (SA_U + SB_U)           // 4736 u32 = 18944 B
#define GEMM_SMEM (4 * STG_U * 4)     // 75776 B

__device__ __forceinline__ void stage_ab(uint32_t* sm,
    const uint32_t* A, const uint32_t* B,
    int m0, int n0u, int ch, int N2, int K2, int tid)
{
    uint32_t* as = sm;
    uint32_t* bs = sm + SA_U;
    const int kp0 = ch << 4;      // A k-pair offset
    const int k0 = ch << 5;       // B k offset
#pragma unroll
    for (int r = 0; r < 2; ++r) {
        int o = tid + (r << 8);
        cp16(&as[(o >> 2) * AS_U + ((o & 3) << 2)],
             A + (size_t)(m0 + (o >> 2)) * K2 + kp0 + ((o & 3) << 2));
        cp16(&bs[(o >> 4) * BS_U + ((o & 15) << 2)],
             B + (size_t)(k0 + (o >> 4)) * N2 + n0u + ((o & 15) << 2));
    }
}

template<int GELU, int HALF_OUT>
__global__ void __launch_bounds__(256, 2) mma_gemm(
    const uint32_t* __restrict__ A, const uint32_t* __restrict__ B,
    const float* __restrict__ bias, void* __restrict__ Cv,
    int N, int K)
{
    extern __shared__ uint32_t smem[];
    const int tid = threadIdx.x;
    const int wid = tid >> 5, lane = tid & 31;
    const int g = lane >> 2, t = lane & 3;
    const int lq = lane & 15, lh = lane >> 4;
    const int wm = wid >> 2, wn = wid & 3;
    const int mw = wm * 64, nw = wn * 32;
    const int m0 = blockIdx.y * 128, n0 = blockIdx.x * 128;
    const int K2 = K >> 1, N2 = N >> 1;
    const int n0u = n0 >> 1, nwu = nw >> 1;

    float acc[4][4][4];
#pragma unroll
    for (int i = 0; i < 4; i++)
#pragma unroll
        for (int j = 0; j < 4; j++)
#pragma unroll
            for (int q = 0; q < 4; q++) acc[i][j][q] = 0.0f;

    const int nch = K >> 5;

#pragma unroll
    for (int s = 0; s < 3; ++s) {
        stage_ab(smem + s * STG_U, A, B, m0, n0u, s, N2, K2, tid);
        CP_COMMIT();
    }

    for (int ch = 0; ch < nch; ++ch) {
        CP_WAIT2();
        __syncthreads();
        if (ch + 3 < nch)
            stage_ab(smem + ((ch + 3) & 3) * STG_U, A, B, m0, n0u, ch + 3, N2, K2, tid);
        CP_COMMIT();

        const uint32_t* As = smem + (ch & 3) * STG_U;
        const uint32_t* Bs = As + SA_U;
#pragma unroll
        for (int ks = 0; ks < 2; ++ks) {
            uint32_t bfr[2][4];
#pragma unroll
            for (int nfp = 0; nfp < 2; ++nfp)
                ldsm4t(&Bs[(ks * 16 + lq) * BS_U + nwu + nfp * 8 + (lh << 2)], bfr[nfp]);
#pragma unroll
            for (int mf = 0; mf < 4; ++mf) {
                uint32_t af[4];
                ldsm4(&As[(mw + mf * 16 + lq) * AS_U + ks * 8 + (lh << 2)], af);
                mma_f16(acc[mf][0], af[0], af[1], af[2], af[3], bfr[0][0], bfr[0][1]);
                mma_f16(acc[mf][1], af[0], af[1], af[2], af[3], bfr[0][2], bfr[0][3]);
                mma_f16(acc[mf][2], af[0], af[1], af[2], af[3], bfr[1][0], bfr[1][1]);
                mma_f16(acc[mf][3], af[0], af[1], af[2], af[3], bfr[1][2], bfr[1][3]);
            }
        }
    }

#pragma unroll
    for (int mf = 0; mf < 4; ++mf) {
        const int row = m0 + mw + mf * 16 + g;
#pragma unroll
        for (int nf = 0; nf < 4; ++nf) {
            const int col = n0 + nw + nf * 8 + t * 2;
            float b0 = 0.f, b1 = 0.f;
            if (bias) { b0 = bias[col]; b1 = bias[col + 1]; }
            float c0 = acc[mf][nf][0] + b0, c1 = acc[mf][nf][1] + b1;
            float c2 = acc[mf][nf][2] + b0, c3 = acc[mf][nf][3] + b1;
            if (GELU) { c0 = gelu_f(c0); c1 = gelu_f(c1); c2 = gelu_f(c2); c3 = gelu_f(c3); }
            if (HALF_OUT) {
                uint32_t* Ch = (uint32_t*)Cv;
                Ch[((size_t)row * N + col) >> 1]       = packh2(c0, c1);
                Ch[((size_t)(row + 8) * N + col) >> 1] = packh2(c2, c3);
            } else {
                float* Cf = (float*)Cv;
                *(float2*)(Cf + (size_t)row * N + col)       = make_float2(c0, c1);
                *(float2*)(Cf + (size_t)(row + 8) * N + col) = make_float2(c2, c3);
            }
        }
    }
}

// ---------------- CPB bias table ----------------
__global__ void cpb_kernel(const float* __restrict__ w1, const float* __restrict__ b1,
                           const float* __restrict__ w2, const float* __restrict__ b2,
                           float* __restrict__ tbl)
{
    int f = blockIdx.x;
    int h = threadIdx.x;
    int i = f / 15, j = f % 15;
    float v0 = 8.0f * (float)(j - 7) / 7.0f;
    float v1 = 8.0f * (float)(i - 7) / 7.0f;
    float c0 = copysignf(log2f(fabsf(v0) + 1.0f) * (1.0f / 3.0f), v0);
    float c1 = copysignf(log2f(fabsf(v1) + 1.0f) * (1.0f / 3.0f), v1);
    float hid = fmaxf(c0 * w1[h] + c1 * w1[512 + h] + b1[h], 0.0f);

    __shared__ float red[512];
    for (int nh = 0; nh < 16; ++nh) {
        red[h] = hid * w2[h * 16 + nh];
        __syncthreads();
        for (int s = 256; s > 0; s >>= 1) {
            if (h < s) red[h] += red[h + s];
            __syncthreads();
        }
        if (h == 0) tbl[f * 16 + nh] = red[0] + b2[nh];
        __syncthreads();
    }
}

// ---------------- shift + window partition gather -> half -------------------
__global__ void gather_xw(const float* __restrict__ x, uint32_t* __restrict__ xw)
{
    size_t idx = (size_t)blockIdx.x * 256 + threadIdx.x;
    if (idx >= (size_t)NROW * 128) return;
    int c4  = (int)(idx & 127);
    int row = (int)(idx >> 7);
    int n = row & 63, bw = row >> 6;
    int win = bw & 63, b = bw >> 6;
    int wh = win >> 3, wwn = win & 7;
    int i = n >> 3, j = n & 7;
    int h = ((wh << 3) + i + 4) & 63;
    int w = ((wwn << 3) + j + 4) & 63;
    float4 vv = *(((const float4*)(x + (size_t)((b << 12) + (h << 6) + w) * C_)) + c4);
    uint2 u;
    u.x = packh2(vv.x, vv.y);
    u.y = packh2(vv.z, vv.w);
    *(uint2*)(xw + (size_t)row * 256 + c4 * 2) = u;
}

// ---------------- tensor-core windowed cosine attention ---------------------
__global__ void __launch_bounds__(128) attn_tc(
    const uint32_t* __restrict__ qkv,
    const float* __restrict__ tau, const float* __restrict__ tbl,
    uint32_t* __restrict__ out)
{
    __shared__ uint32_t Qh[64 * 17];
    __shared__ uint32_t Kh[64 * 17];
    __shared__ __half sVt[32 * 72];
    __shared__ float qn[64], kn[64];

    const int blk = blockIdx.x;
    const int head = blk & 15, bw = blk >> 4;
    const int win = bw & 63;
    const int tid = threadIdx.x;
    const int wid = tid >> 5, lane = tid & 31;
    const int g = lane >> 2, t = lane & 3;
    const int mr = wid << 4;

    const uint32_t* base = qkv + (size_t)(bw << 6) * 768 + (head << 4);

    for (int i = tid; i < 1024; i += 128) {
        int tok = i >> 4, c = i & 15;
        Qh[tok * 17 + c] = base[(size_t)tok * 768 + c];
        Kh[tok * 17 + c] = base[(size_t)tok * 768 + 256 + c];
    }
    for (int i = tid; i < 1024; i += 128) {
        int tok = i >> 4, dp = i & 15;
        uint32_t u = base[(size_t)tok * 768 + 512 + dp];
        __half2 h = *(__half2*)&u;
        sVt[(dp * 2) * 72 + tok]     = __low2half(h);
        sVt[(dp * 2 + 1) * 72 + tok] = __high2half(h);
    }
    __syncthreads();

    {
        int tok = tid & 63;
        const uint32_t* src = (tid < 64) ? &Qh[tok * 17] : &Kh[tok * 17];
        float s = 0.0f;
#pragma unroll
        for (int c = 0; c < 16; ++c) {
            float2 f = __half22float2(*(__half2*)&src[c]);
            s = fmaf(f.x, f.x, fmaf(f.y, f.y, s));
        }
        if (tid < 64) qn[tok] = sqrtf(s); else kn[tok] = sqrtf(s);
    }
    __syncthreads();

    float sacc[8][4];
#pragma unroll
    for (int nf = 0; nf < 8; ++nf)
#pragma unroll
        for (int e = 0; e < 4; ++e) sacc[nf][e] = 0.0f;

    uint32_t aq[2][4];
#pragma unroll
    for (int kb = 0; kb < 2; ++kb) {
        aq[kb][0] = Qh[(mr + g) * 17 + kb * 8 + t];
        aq[kb][1] = Qh[(mr + g + 8) * 17 + kb * 8 + t];
        aq[kb][2] = Qh[(mr + g) * 17 + kb * 8 + t + 4];
        aq[kb][3] = Qh[(mr + g + 8) * 17 + kb * 8 + t + 4];
    }
#pragma unroll
    for (int nf = 0; nf < 8; ++nf) {
        const int col = (nf << 3) + g;
#pragma unroll
        for (int kb = 0; kb < 2; ++kb) {
            uint32_t b0 = Kh[col * 17 + kb * 8 + t];
            uint32_t b1 = Kh[col * 17 + kb * 8 + t + 4];
            mma_f16(sacc[nf], aq[kb][0], aq[kb][1], aq[kb][2], aq[kb][3], b0, b1);
        }
    }

    const float ls = fmaxf(tau[head] + 2.302585092994046f, 0.01f);
    const int whb = (win >> 3) << 3, wwb = (win & 7) << 3;
    const int r1 = mr + g, r2 = mr + g + 8;
    float mx1 = -1e30f, mx2 = -1e30f;
#pragma unroll
    for (int nf = 0; nf < 8; ++nf) {
#pragma unroll
        for (int e = 0; e < 4; ++e) {
            const int r = (e < 2) ? r1 : r2;
            const int c = (nf << 3) + (t << 1) + (e & 1);
            float a = sacc[nf][e] / fmaxf(qn[r] * kn[c], 1e-6f) * ls;
            int dr = (r >> 3) - (c >> 3), dc = (r & 7) - (c & 7);
            float bsv = tbl[((dr + 7) * 15 + (dc + 7)) * 16 + head];
            a += 16.0f / (1.0f + expf(-bsv));
            int hn = whb + (r >> 3), wn = wwb + (r & 7);
            int hm = whb + (c >> 3), wm = wwb + (c & 7);
            int rn = (hn < 56 ? 0 : (hn < 60 ? 1 : 2)) * 3 + (wn < 56 ? 0 : (wn < 60 ? 1 : 2));
            int rm = (hm < 56 ? 0 : (hm < 60 ? 1 : 2)) * 3 + (wm < 56 ? 0 : (wm < 60 ? 1 : 2));
            if (rn != rm) a -= 100.0f;
            sacc[nf][e] = a;
            if (e < 2) mx1 = fmaxf(mx1, a); else mx2 = fmaxf(mx2, a);
        }
    }
#pragma unroll
    for (int o = 1; o <= 2; o <<= 1) {
        mx1 = fmaxf(mx1, __shfl_xor_sync(0xffffffffu, mx1, o));
        mx2 = fmaxf(mx2, __shfl_xor_sync(0xffffffffu, mx2, o));
    }
    float s1 = 0.0f, s2 = 0.0f;
#pragma unroll
    for (int nf = 0; nf < 8; ++nf) {
        float e0 = expf(sacc[nf][0] - mx1);
        float e1 = expf(sacc[nf][1] - mx1);
        float e2 = expf(sacc[nf][2] - mx2);
        float e3 = expf(sacc[nf][3] - mx2);
        sacc[nf][0] = e0; sacc[nf][1] = e1; sacc[nf][2] = e2; sacc[nf][3] = e3;
        s1 += e0 + e1; s2 += e2 + e3;
    }
#pragma unroll
    for (int o = 1; o <= 2; o <<= 1) {
        s1 += __shfl_xor_sync(0xffffffffu, s1, o);
        s2 += __shfl_xor_sync(0xffffffffu, s2, o);
    }
    const float inv1 = 1.0f / s1, inv2 = 1.0f / s2;

    float oacc[4][4];
#pragma unroll
    for (int nf = 0; nf < 4; ++nf)
#pragma unroll
        for (int e = 0; e < 4; ++e) oacc[nf][e] = 0.0f;

    const uint32_t* vt32 = (const uint32_t*)sVt;
#pragma unroll
    for (int kc = 0; kc < 4; ++kc) {
        uint32_t a0 = packh2(sacc[kc * 2][0],     sacc[kc * 2][1]);
        uint32_t a1 = packh2(sacc[kc * 2][2],     sacc[kc * 2][3]);
        uint32_t a2 = packh2(sacc[kc * 2 + 1][0], sacc[kc * 2 + 1][1]);
        uint32_t a3 = packh2(sacc[kc * 2 + 1][2], sacc[kc * 2 + 1][3]);
#pragma unroll
        for (int nf = 0; nf < 4; ++nf) {
            const int d = (nf << 3) + g;
            uint32_t b0 = vt32[d * 36 + kc * 8 + t];
            uint32_t b1 = vt32[d * 36 + kc * 8 + t + 4];
            mma_f16(oacc[nf], a0, a1, a2, a3, b0, b1);
        }
    }

    const size_t orow1 = (size_t)((bw << 6) + r1) * 256 + (head << 4);
    const size_t orow2 = (size_t)((bw << 6) + r2) * 256 + (head << 4);
#pragma unroll
    for (int nf = 0; nf < 4; ++nf) {
        out[orow1 + (nf << 2) + t] = packh2(oacc[nf][0] * inv1, oacc[nf][1] * inv1);
        out[orow2 + (nf << 2) + t] = packh2(oacc[nf][2] * inv2, oacc[nf][3] * inv2);
    }
}

// ---------------- (optional gather) + LayerNorm + residual ----------------
__global__ void __launch_bounds__(128) ln_res_kernel(
    const float* __restrict__ src, const float* __restrict__ resid,
    const float* __restrict__ g, const float* __restrict__ bb,
    float* __restrict__ dst, uint32_t* __restrict__ dst_half, int gather)
{
    int r = blockIdx.x, tid = threadIdx.x;
    int srow = r;
    if (gather) {
        int b = r >> 12, hw = r & 4095;
        int h = hw >> 6, w = hw & 63;
        int hh = (h + 60) & 63, wv = (w + 60) & 63;
        srow = (((b << 6) + ((hh >> 3) << 3) + (wv >> 3)) << 6) + ((hh & 7) << 3) + (wv & 7);
    }
    float4 val = ((const float4*)(src + (size_t)srow * C_))[tid];
    __shared__ float sh[4];

    float s = val.x + val.y + val.z + val.w;
#pragma unroll
    for (int o = 16; o; o >>= 1) s += __shfl_xor_sync(0xffffffffu, s, o);
    if ((tid & 31) == 0) sh[tid >> 5] = s;
    __syncthreads();
    float mean = (sh[0] + sh[1] + sh[2] + sh[3]) * (1.0f / 512.0f);
    __syncthreads();

    float dx = val.x - mean, dy = val.y - mean, dz = val.z - mean, dw = val.w - mean;
    float s2 = dx * dx + dy * dy + dz * dz + dw * dw;
#pragma unroll
    for (int o = 16; o; o >>= 1) s2 += __shfl_xor_sync(0xffffffffu, s2, o);
    if ((tid & 31) == 0) sh[tid >> 5] = s2;
    __syncthreads();
    float var = (sh[0] + sh[1] + sh[2] + sh[3]) * (1.0f / 512.0f);
    float rstd = rsqrtf(var + 1e-6f);

    float4 gg = ((const float4*)g)[tid];
    float4 bv = ((const float4*)bb)[tid];
    float4 xr = ((const float4*)(resid + (size_t)r * C_))[tid];
    float4 o;
    o.x = xr.x + dx * rstd * gg.x + bv.x;
    o.y = xr.y + dy * rstd * gg.y + bv.y;
    o.z = xr.z + dz * rstd * gg.z + bv.z;
    o.w = xr.w + dw * rstd * gg.w + bv.w;
    ((float4*)(dst + (size_t)r * C_))[tid] = o;
    if (dst_half) {
        uint2 u;
        u.x = packh2(o.x, o.y);
        u.y = packh2(o.z, o.w);
        *(uint2*)(dst_half + (size_t)r * 256 + tid * 2) = u;
    }
}

// ---------------- host launch ----------------
extern "C" void kernel_launch(void* const* d_in, const int* in_sizes, int n_in,
                              void* d_out, int out_size)
{
    const float* x      = (const float*)d_in[0];
    const float* q_w    = (const float*)d_in[1];
    const float* q_b    = (const float*)d_in[2];
    const float* k_w    = (const float*)d_in[3];
    const float* v_w    = (const float*)d_in[4];
    const float* v_b    = (const float*)d_in[5];
    const float* proj_w = (const float*)d_in[6];
    const float* proj_b = (const float*)d_in[7];
    const float* tau    = (const float*)d_in[8];
    const float* cpb_w1 = (const float*)d_in[9];
    const float* cpb_b1 = (const float*)d_in[10];
    const float* cpb_w2 = (const float*)d_in[11];
    const float* cpb_b2 = (const float*)d_in[12];
    const float* n1g    = (const float*)d_in[13];
    const float* n1b    = (const float*)d_in[14];
    const float* n2g    = (const float*)d_in[15];
    const float* n2b    = (const float*)d_in[16];
    const float* w1     = (const float*)d_in[17];
    const float* b1     = (const float*)d_in[18];
    const float* w2     = (const float*)d_in[19];
    const float* b2     = (const float*)d_in[20];
    float* out = (float*)d_out;

    float *xwf, *q, *v, *hf, *wrf, *tbl, *qkvb;
    cudaGetSymbolAddress((void**)&xwf,  g_xw);
    cudaGetSymbolAddress((void**)&q,    g_q);
    cudaGetSymbolAddress((void**)&v,    g_v);
    cudaGetSymbolAddress((void**)&hf,   g_h);
    cudaGetSymbolAddress((void**)&wrf,  g_wr);
    cudaGetSymbolAddress((void**)&tbl,  g_tbl);
    cudaGetSymbolAddress((void**)&qkvb, g_qkvb);

    uint32_t* xw   = (uint32_t*)xwf;
    uint32_t* qkvh = (uint32_t*)hf;
    uint32_t* hb   = (uint32_t*)(hf + 50331648);
    uint32_t* wr   = (uint32_t*)wrf;

    uint32_t* wqkv = wr;                 // [512][768] u32
    uint32_t* wp   = wr + 393216;        // [512][256]
    uint32_t* wf1  = wr + 524288;        // [512][1024]
    uint32_t* wf2  = wr + 1048576;       // [2048][256]

    cudaFuncSetAttribute((const void*)mma_gemm<0, 0>,
                         cudaFuncAttributeMaxDynamicSharedMemorySize, GEMM_SMEM);
    cudaFuncSetAttribute((const void*)mma_gemm<0, 1>,
                         cudaFuncAttributeMaxDynamicSharedMemorySize, GEMM_SMEM);
    cudaFuncSetAttribute((const void*)mma_gemm<1, 1>,
                         cudaFuncAttributeMaxDynamicSharedMemorySize, GEMM_SMEM);

    // 1. merged prep
    pack_all<<<1542, 256>>>(q_w, k_w, v_w, proj_w, w1, w2, q_b, v_b,
                            wqkv, wp, wf1, wf2, qkvb);
    // 2. CPB table
    cpb_kernel<<<225, 512>>>(cpb_w1, cpb_b1, cpb_w2, cpb_b2, tbl);
    // 3. gather
    gather_xw<<<(NROW * 128) / 256, 256>>>(x, xw);
    // 4. fused QKV
    mma_gemm<0, 1><<<dim3(12, 512), 256, GEMM_SMEM>>>(xw, wqkv, qkvb, qkvh, 1536, 512);
    // 5. attention
    attn_tc<<<16384, 128>>>(qkvh, tau, tbl, xw);
    // 6. proj  (ncu -s 5 -c 1 captures this launch)
    mma_gemm<0, 0><<<dim3(4, 512), 256, GEMM_SMEM>>>(xw, wp, proj_b, q, 512, 512);
    // 7. gather + LN1 + residual
    ln_res_kernel<<<NTOK, 128>>>(q, x, n1g, n1b, v, xw, 1);
    // 8. fc1 + gelu
    mma_gemm<1, 1><<<dim3(16, 512), 256, GEMM_SMEM>>>(xw, wf1, b1, hb, 2048, 512);
    // 9. fc2
    mma_gemm<0, 0><<<dim3(4, 512), 256, GEMM_SMEM>>>(hb, wf2, b2, q, 512, 2048);
    // 10. LN2 + residual
    ln_res_kernel<<<NTOK, 128>>>(q, v, n2g, n2b, out, (uint32_t*)nullptr, 0);
}

// round 10
// speedup vs baseline: 5.7037x; 1.0010x over previous
#include <cuda_runtime.h>
#include <cuda_fp16.h>
#include <math.h>
#include <stdint.h>

// Problem constants
#define B_   16
#define H_   64
#define W_   64
#define C_   512
#define NH_  16
#define HD_  32
#define NTOK 65536
#define NWIN 64
#define NROW 65536

// ---------------- device scratch (allocation-free) ----------------
__device__ float g_xw[(size_t)NROW * C_];    // half activations (u32-packed), reused
__device__ float g_q [(size_t)NROW * C_];    // fp32 proj-out / fc2-out
__device__ float g_v [(size_t)NROW * C_];    // fp32 x1
__device__ float g_h [(size_t)NROW * 2048];  // qkv half (front) + mlp hidden half
__device__ float g_wr[3145728];              // plain-half weights (u32 view)
__device__ float g_tbl[225 * 16];
__device__ float g_qkvb[1536];

// ---------------- helpers ----------------
__device__ __forceinline__ uint32_t smem_u32(const void* p) {
    uint32_t a;
    asm("{ .reg .u64 t; cvta.to.shared.u64 t, %1; cvt.u32.u64 %0, t; }" : "=r"(a) : "l"(p));
    return a;
}
__device__ __forceinline__ uint32_t packh2(float lo, float hi) {
    __half2 h = __floats2half2_rn(lo, hi);
    return *reinterpret_cast<uint32_t*>(&h);
}
__device__ __forceinline__ void cp16(void* sdst, const void* gsrc) {
    uint32_t s = smem_u32(sdst);
    asm volatile("cp.async.cg.shared.global [%0], [%1], 16;" :: "r"(s), "l"(gsrc) : "memory");
}
#define CP_COMMIT() asm volatile("cp.async.commit_group;" ::: "memory")
#define CP_WAIT2()  asm volatile("cp.async.wait_group 2;" ::: "memory")

__device__ __forceinline__ void ldsm4(const void* p, uint32_t* r) {
    uint32_t a = smem_u32(p);
    asm volatile("ldmatrix.sync.aligned.m8n8.x4.shared.b16 {%0,%1,%2,%3}, [%4];"
        : "=r"(r[0]), "=r"(r[1]), "=r"(r[2]), "=r"(r[3]) : "r"(a));
}
__device__ __forceinline__ void ldsm4t(const void* p, uint32_t* r) {
    uint32_t a = smem_u32(p);
    asm volatile("ldmatrix.sync.aligned.m8n8.x4.trans.shared.b16 {%0,%1,%2,%3}, [%4];"
        : "=r"(r[0]), "=r"(r[1]), "=r"(r[2]), "=r"(r[3]) : "r"(a));
}
__device__ __forceinline__ void mma_f16(float* c, uint32_t a0, uint32_t a1,
                                        uint32_t a2, uint32_t a3,
                                        uint32_t b0, uint32_t b1) {
    asm volatile(
        "mma.sync.aligned.m16n8k16.row.col.f32.f16.f16.f32 "
        "{%0,%1,%2,%3}, {%4,%5,%6,%7}, {%8,%9}, {%0,%1,%2,%3};"
        : "+f"(c[0]), "+f"(c[1]), "+f"(c[2]), "+f"(c[3])
        : "r"(a0), "r"(a1), "r"(a2), "r"(a3), "r"(b0), "r"(b1));
}
__device__ __forceinline__ float gelu_f(float t) {
    return 0.5f * t * (1.0f + tanhf(0.7978845608028654f * (t + 0.044715f * t * t * t)));
}

// ---------------- merged prep: all weights f32 -> plain half, + fused bias ---
__device__ __forceinline__ void pack_one(const float* __restrict__ src, uint32_t* __restrict__ dst,
                                         int N, int dstN2, int coloff, int local)
{
    int n8c = N >> 3;
    int k = local / n8c, n8 = local % n8c;
    const float4* s = (const float4*)(src + (size_t)k * N + (n8 << 3));
    float4 f0 = s[0], f1 = s[1];
    uint4 u;
    u.x = packh2(f0.x, f0.y);
    u.y = packh2(f0.z, f0.w);
    u.z = packh2(f1.x, f1.y);
    u.w = packh2(f1.z, f1.w);
    *(uint4*)(dst + (size_t)k * dstN2 + coloff + (n8 << 2)) = u;
}

__global__ void pack_all(const float* __restrict__ q_w, const float* __restrict__ k_w,
                         const float* __restrict__ v_w, const float* __restrict__ p_w,
                         const float* __restrict__ w1, const float* __restrict__ w2,
                         const float* __restrict__ qb, const float* __restrict__ vb,
                         uint32_t* __restrict__ wqkv, uint32_t* __restrict__ wp,
                         uint32_t* __restrict__ wf1, uint32_t* __restrict__ wf2,
                         float* __restrict__ qkvb)
{
    int idx = blockIdx.x * 256 + threadIdx.x;
    if (idx < 32768)        pack_one(q_w, wqkv, 512, 768, 0,   idx);
    else if (idx < 65536)   pack_one(k_w, wqkv, 512, 768, 256, idx - 32768);
    else if (idx < 98304)   pack_one(v_w, wqkv, 512, 768, 512, idx - 65536);
    else if (idx < 131072)  pack_one(p_w, wp,   512, 256, 0,   idx - 98304);
    else if (idx < 262144)  pack_one(w1,  wf1, 2048, 1024, 0,  idx - 131072);
    else if (idx < 393216)  pack_one(w2,  wf2,  512, 256, 0,   idx - 262144);
    else if (idx < 394752) {
        int i = idx - 393216;
        float v = 0.0f;
        if (i < 512) v = qb[i];
        else if (i >= 1024) v = vb[i - 1024];
        qkvb[i] = v;
    }
}

// ---------------- fp16 mma.sync GEMM with ldmatrix + frag hoisting ----------
#define AS_U 20                       // u32 per A smem row (16 data + 4 pad)
#define BS_U 68                       // u32 per B smem k-row (64 data + 4 pad)
#define SA_U (128 * AS_U)             // 2560
#define SB_U (32 * BS_U)              // 2176
#define STG_U (SA_U + SB_U)           // 4736 u32 = 18944 B
#define GEMM_SMEM (4 * STG_U * 4)     // 75776 B

__device__ __forceinline__ void stage_ab(uint32_t* sm,
    const uint32_t* A, const uint32_t* B,
    int m0, int n0u, int ch, int N2, int K2, int tid)
{
    uint32_t* as = sm;
    uint32_t* bs = sm + SA_U;
    const int kp0 = ch << 4;      // A k-pair offset
    const int k0 = ch << 5;       // B k offset
#pragma unroll
    for (int r = 0; r < 2; ++r) {
        int o = tid + (r << 8);
        cp16(&as[(o >> 2) * AS_U + ((o & 3) << 2)],
             A + (size_t)(m0 + (o >> 2)) * K2 + kp0 + ((o & 3) << 2));
        cp16(&bs[(o >> 4) * BS_U + ((o & 15) << 2)],
             B + (size_t)(k0 + (o >> 4)) * N2 + n0u + ((o & 15) << 2));
    }
}

template<int GELU, int HALF_OUT>
__global__ void __launch_bounds__(256, 2) mma_gemm(
    const uint32_t* __restrict__ A, const uint32_t* __restrict__ B,
    const float* __restrict__ bias, void* __restrict__ Cv,
    int N, int K)
{
    extern __shared__ uint32_t smem[];
    const int tid = threadIdx.x;
    const int wid = tid >> 5, lane = tid & 31;
    const int g = lane >> 2, t = lane & 3;
    const int lq = lane & 15, lh = lane >> 4;
    const int wm = wid >> 2, wn = wid & 3;
    const int mw = wm * 64, nw = wn * 32;
    const int m0 = blockIdx.y * 128, n0 = blockIdx.x * 128;
    const int K2 = K >> 1, N2 = N >> 1;
    const int n0u = n0 >> 1, nwu = nw >> 1;

    float acc[4][4][4];
#pragma unroll
    for (int i = 0; i < 4; i++)
#pragma unroll
        for (int j = 0; j < 4; j++)
#pragma unroll
            for (int q = 0; q < 4; q++) acc[i][j][q] = 0.0f;

    const int nch = K >> 5;

#pragma unroll
    for (int s = 0; s < 3; ++s) {
        stage_ab(smem + s * STG_U, A, B, m0, n0u, s, N2, K2, tid);
        CP_COMMIT();
    }

    for (int ch = 0; ch < nch; ++ch) {
        CP_WAIT2();
        __syncthreads();
        if (ch + 3 < nch)
            stage_ab(smem + ((ch + 3) & 3) * STG_U, A, B, m0, n0u, ch + 3, N2, K2, tid);
        CP_COMMIT();

        const uint32_t* As = smem + (ch & 3) * STG_U;
        const uint32_t* Bs = As + SA_U;

        // hoist ALL B fragments for both k-steps (round-7 address expressions)
        uint32_t bfr[2][2][4];
#pragma unroll
        for (int ks = 0; ks < 2; ++ks)
#pragma unroll
            for (int nfp = 0; nfp < 2; ++nfp)
                ldsm4t(&Bs[(ks * 16 + lq) * BS_U + nwu + nfp * 8 + (lh << 2)], bfr[ks][nfp]);

#pragma unroll
        for (int mf = 0; mf < 4; ++mf) {
            uint32_t af[2][4];
#pragma unroll
            for (int ks = 0; ks < 2; ++ks)
                ldsm4(&As[(mw + mf * 16 + lq) * AS_U + ks * 8 + (lh << 2)], af[ks]);
#pragma unroll
            for (int ks = 0; ks < 2; ++ks) {
                mma_f16(acc[mf][0], af[ks][0], af[ks][1], af[ks][2], af[ks][3],
                        bfr[ks][0][0], bfr[ks][0][1]);
                mma_f16(acc[mf][1], af[ks][0], af[ks][1], af[ks][2], af[ks][3],
                        bfr[ks][0][2], bfr[ks][0][3]);
                mma_f16(acc[mf][2], af[ks][0], af[ks][1], af[ks][2], af[ks][3],
                        bfr[ks][1][0], bfr[ks][1][1]);
                mma_f16(acc[mf][3], af[ks][0], af[ks][1], af[ks][2], af[ks][3],
                        bfr[ks][1][2], bfr[ks][1][3]);
            }
        }
    }

#pragma unroll
    for (int mf = 0; mf < 4; ++mf) {
        const int row = m0 + mw + mf * 16 + g;
#pragma unroll
        for (int nf = 0; nf < 4; ++nf) {
            const int col = n0 + nw + nf * 8 + t * 2;
            float b0 = 0.f, b1 = 0.f;
            if (bias) { b0 = bias[col]; b1 = bias[col + 1]; }
            float c0 = acc[mf][nf][0] + b0, c1 = acc[mf][nf][1] + b1;
            float c2 = acc[mf][nf][2] + b0, c3 = acc[mf][nf][3] + b1;
            if (GELU) { c0 = gelu_f(c0); c1 = gelu_f(c1); c2 = gelu_f(c2); c3 = gelu_f(c3); }
            if (HALF_OUT) {
                uint32_t* Ch = (uint32_t*)Cv;
                Ch[((size_t)row * N + col) >> 1]       = packh2(c0, c1);
                Ch[((size_t)(row + 8) * N + col) >> 1] = packh2(c2, c3);
            } else {
                float* Cf = (float*)Cv;
                *(float2*)(Cf + (size_t)row * N + col)       = make_float2(c0, c1);
                *(float2*)(Cf + (size_t)(row + 8) * N + col) = make_float2(c2, c3);
            }
        }
    }
}

// ---------------- CPB bias table ----------------
__global__ void cpb_kernel(const float* __restrict__ w1, const float* __restrict__ b1,
                           const float* __restrict__ w2, const float* __restrict__ b2,
                           float* __restrict__ tbl)
{
    int f = blockIdx.x;
    int h = threadIdx.x;
    int i = f / 15, j = f % 15;
    float v0 = 8.0f * (float)(j - 7) / 7.0f;
    float v1 = 8.0f * (float)(i - 7) / 7.0f;
    float c0 = copysignf(log2f(fabsf(v0) + 1.0f) * (1.0f / 3.0f), v0);
    float c1 = copysignf(log2f(fabsf(v1) + 1.0f) * (1.0f / 3.0f), v1);
    float hid = fmaxf(c0 * w1[h] + c1 * w1[512 + h] + b1[h], 0.0f);

    __shared__ float red[512];
    for (int nh = 0; nh < 16; ++nh) {
        red[h] = hid * w2[h * 16 + nh];
        __syncthreads();
        for (int s = 256; s > 0; s >>= 1) {
            if (h < s) red[h] += red[h + s];
            __syncthreads();
        }
        if (h == 0) tbl[f * 16 + nh] = red[0] + b2[nh];
        __syncthreads();
    }
}

// ---------------- shift + window partition gather -> half -------------------
__global__ void gather_xw(const float* __restrict__ x, uint32_t* __restrict__ xw)
{
    size_t idx = (size_t)blockIdx.x * 256 + threadIdx.x;
    if (idx >= (size_t)NROW * 128) return;
    int c4  = (int)(idx & 127);
    int row = (int)(idx >> 7);
    int n = row & 63, bw = row >> 6;
    int win = bw & 63, b = bw >> 6;
    int wh = win >> 3, wwn = win & 7;
    int i = n >> 3, j = n & 7;
    int h = ((wh << 3) + i + 4) & 63;
    int w = ((wwn << 3) + j + 4) & 63;
    float4 vv = *(((const float4*)(x + (size_t)((b << 12) + (h << 6) + w) * C_)) + c4);
    uint2 u;
    u.x = packh2(vv.x, vv.y);
    u.y = packh2(vv.z, vv.w);
    *(uint2*)(xw + (size_t)row * 256 + c4 * 2) = u;
}

// ---------------- tensor-core windowed cosine attention ---------------------
__global__ void __launch_bounds__(128) attn_tc(
    const uint32_t* __restrict__ qkv,
    const float* __restrict__ tau, const float* __restrict__ tbl,
    uint32_t* __restrict__ out)
{
    __shared__ uint32_t Qh[64 * 17];
    __shared__ uint32_t Kh[64 * 17];
    __shared__ __half sVt[32 * 72];
    __shared__ float qn[64], kn[64];

    const int blk = blockIdx.x;
    const int head = blk & 15, bw = blk >> 4;
    const int win = bw & 63;
    const int tid = threadIdx.x;
    const int wid = tid >> 5, lane = tid & 31;
    const int g = lane >> 2, t = lane & 3;
    const int mr = wid << 4;

    const uint32_t* base = qkv + (size_t)(bw << 6) * 768 + (head << 4);

    for (int i = tid; i < 1024; i += 128) {
        int tok = i >> 4, c = i & 15;
        Qh[tok * 17 + c] = base[(size_t)tok * 768 + c];
        Kh[tok * 17 + c] = base[(size_t)tok * 768 + 256 + c];
    }
    for (int i = tid; i < 1024; i += 128) {
        int tok = i >> 4, dp = i & 15;
        uint32_t u = base[(size_t)tok * 768 + 512 + dp];
        __half2 h = *(__half2*)&u;
        sVt[(dp * 2) * 72 + tok]     = __low2half(h);
        sVt[(dp * 2 + 1) * 72 + tok] = __high2half(h);
    }
    __syncthreads();

    {
        int tok = tid & 63;
        const uint32_t* src = (tid < 64) ? &Qh[tok * 17] : &Kh[tok * 17];
        float s = 0.0f;
#pragma unroll
        for (int c = 0; c < 16; ++c) {
            float2 f = __half22float2(*(__half2*)&src[c]);
            s = fmaf(f.x, f.x, fmaf(f.y, f.y, s));
        }
        if (tid < 64) qn[tok] = sqrtf(s); else kn[tok] = sqrtf(s);
    }
    __syncthreads();

    float sacc[8][4];
#pragma unroll
    for (int nf = 0; nf < 8; ++nf)
#pragma unroll
        for (int e = 0; e < 4; ++e) sacc[nf][e] = 0.0f;

    uint32_t aq[2][4];
#pragma unroll
    for (int kb = 0; kb < 2; ++kb) {
        aq[kb][0] = Qh[(mr + g) * 17 + kb * 8 + t];
        aq[kb][1] = Qh[(mr + g + 8) * 17 + kb * 8 + t];
        aq[kb][2] = Qh[(mr + g) * 17 + kb * 8 + t + 4];
        aq[kb][3] = Qh[(mr + g + 8) * 17 + kb * 8 + t + 4];
    }
#pragma unroll
    for (int nf = 0; nf < 8; ++nf) {
        const int col = (nf << 3) + g;
#pragma unroll
        for (int kb = 0; kb < 2; ++kb) {
            uint32_t b0 = Kh[col * 17 + kb * 8 + t];
            uint32_t b1 = Kh[col * 17 + kb * 8 + t + 4];
            mma_f16(sacc[nf], aq[kb][0], aq[kb][1], aq[kb][2], aq[kb][3], b0, b1);
        }
    }

    const float ls = fmaxf(tau[head] + 2.302585092994046f, 0.01f);
    const int whb = (win >> 3) << 3, wwb = (win & 7) << 3;
    const int r1 = mr + g, r2 = mr + g + 8;
    float mx1 = -1e30f, mx2 = -1e30f;
#pragma unroll
    for (int nf = 0; nf < 8; ++nf) {
#pragma unroll
        for (int e = 0; e < 4; ++e) {
            const int r = (e < 2) ? r1 : r2;
            const int c = (nf << 3) + (t << 1) + (e & 1);
            float a = sacc[nf][e] / fmaxf(qn[r] * kn[c], 1e-6f) * ls;
            int dr = (r >> 3) - (c >> 3), dc = (r & 7) - (c & 7);
            float bsv = tbl[((dr + 7) * 15 + (dc + 7)) * 16 + head];
            a += 16.0f / (1.0f + expf(-bsv));
            int hn = whb + (r >> 3), wn = wwb + (r & 7);
            int hm = whb + (c >> 3), wm = wwb + (c & 7);
            int rn = (hn < 56 ? 0 : (hn < 60 ? 1 : 2)) * 3 + (wn < 56 ? 0 : (wn < 60 ? 1 : 2));
            int rm = (hm < 56 ? 0 : (hm < 60 ? 1 : 2)) * 3 + (wm < 56 ? 0 : (wm < 60 ? 1 : 2));
            if (rn != rm) a -= 100.0f;
            sacc[nf][e] = a;
            if (e < 2) mx1 = fmaxf(mx1, a); else mx2 = fmaxf(mx2, a);
        }
    }
#pragma unroll
    for (int o = 1; o <= 2; o <<= 1) {
        mx1 = fmaxf(mx1, __shfl_xor_sync(0xffffffffu, mx1, o));
        mx2 = fmaxf(mx2, __shfl_xor_sync(0xffffffffu, mx2, o));
    }
    float s1 = 0.0f, s2 = 0.0f;
#pragma unroll
    for (int nf = 0; nf < 8; ++nf) {
        float e0 = expf(sacc[nf][0] - mx1);
        float e1 = expf(sacc[nf][1] - mx1);
        float e2 = expf(sacc[nf][2] - mx2);
        float e3 = expf(sacc[nf][3] - mx2);
        sacc[nf][0] = e0; sacc[nf][1] = e1; sacc[nf][2] = e2; sacc[nf][3] = e3;
        s1 += e0 + e1; s2 += e2 + e3;
    }
#pragma unroll
    for (int o = 1; o <= 2; o <<= 1) {
        s1 += __shfl_xor_sync(0xffffffffu, s1, o);
        s2 += __shfl_xor_sync(0xffffffffu, s2, o);
    }
    const float inv1 = 1.0f / s1, inv2 = 1.0f / s2;

    float oacc[4][4];
#pragma unroll
    for (int nf = 0; nf < 4; ++nf)
#pragma unroll
        for (int e = 0; e < 4; ++e) oacc[nf][e] = 0.0f;

    const uint32_t* vt32 = (const uint32_t*)sVt;
#pragma unroll
    for (int kc = 0; kc < 4; ++kc) {
        uint32_t a0 = packh2(sacc[kc * 2][0],     sacc[kc * 2][1]);
        uint32_t a1 = packh2(sacc[kc * 2][2],     sacc[kc * 2][3]);
        uint32_t a2 = packh2(sacc[kc * 2 + 1][0], sacc[kc * 2 + 1][1]);
        uint32_t a3 = packh2(sacc[kc * 2 + 1][2], sacc[kc * 2 + 1][3]);
#pragma unroll
        for (int nf = 0; nf < 4; ++nf) {
            const int d = (nf << 3) + g;
            uint32_t b0 = vt32[d * 36 + kc * 8 + t];
            uint32_t b1 = vt32[d * 36 + kc * 8 + t + 4];
            mma_f16(oacc[nf], a0, a1, a2, a3, b0, b1);
        }
    }

    const size_t orow1 = (size_t)((bw << 6) + r1) * 256 + (head << 4);
    const size_t orow2 = (size_t)((bw << 6) + r2) * 256 + (head << 4);
#pragma unroll
    for (int nf = 0; nf < 4; ++nf) {
        out[orow1 + (nf << 2) + t] = packh2(oacc[nf][0] * inv1, oacc[nf][1] * inv1);
        out[orow2 + (nf << 2) + t] = packh2(oacc[nf][2] * inv2, oacc[nf][3] * inv2);
    }
}

// ---------------- (optional gather) + LayerNorm + residual ----------------
__global__ void __launch_bounds__(128) ln_res_kernel(
    const float* __restrict__ src, const float* __restrict__ resid,
    const float* __restrict__ g, const float* __restrict__ bb,
    float* __restrict__ dst, uint32_t* __restrict__ dst_half, int gather)
{
    int r = blockIdx.x, tid = threadIdx.x;
    int srow = r;
    if (gather) {
        int b = r >> 12, hw = r & 4095;
        int h = hw >> 6, w = hw & 63;
        int hh = (h + 60) & 63, wv = (w + 60) & 63;
        srow = (((b << 6) + ((hh >> 3) << 3) + (wv >> 3)) << 6) + ((hh & 7) << 3) + (wv & 7);
    }
    float4 val = ((const float4*)(src + (size_t)srow * C_))[tid];
    __shared__ float sh[4];

    float s = val.x + val.y + val.z + val.w;
#pragma unroll
    for (int o = 16; o; o >>= 1) s += __shfl_xor_sync(0xffffffffu, s, o);
    if ((tid & 31) == 0) sh[tid >> 5] = s;
    __syncthreads();
    float mean = (sh[0] + sh[1] + sh[2] + sh[3]) * (1.0f / 512.0f);
    __syncthreads();

    float dx = val.x - mean, dy = val.y - mean, dz = val.z - mean, dw = val.w - mean;
    float s2 = dx * dx + dy * dy + dz * dz + dw * dw;
#pragma unroll
    for (int o = 16; o; o >>= 1) s2 += __shfl_xor_sync(0xffffffffu, s2, o);
    if ((tid & 31) == 0) sh[tid >> 5] = s2;
    __syncthreads();
    float var = (sh[0] + sh[1] + sh[2] + sh[3]) * (1.0f / 512.0f);
    float rstd = rsqrtf(var + 1e-6f);

    float4 gg = ((const float4*)g)[tid];
    float4 bv = ((const float4*)bb)[tid];
    float4 xr = ((const float4*)(resid + (size_t)r * C_))[tid];
    float4 o;
    o.x = xr.x + dx * rstd * gg.x + bv.x;
    o.y = xr.y + dy * rstd * gg.y + bv.y;
    o.z = xr.z + dz * rstd * gg.z + bv.z;
    o.w = xr.w + dw * rstd * gg.w + bv.w;
    ((float4*)(dst + (size_t)r * C_))[tid] = o;
    if (dst_half) {
        uint2 u;
        u.x = packh2(o.x, o.y);
        u.y = packh2(o.z, o.w);
        *(uint2*)(dst_half + (size_t)r * 256 + tid * 2) = u;
    }
}

// ---------------- host launch ----------------
extern "C" void kernel_launch(void* const* d_in, const int* in_sizes, int n_in,
                              void* d_out, int out_size)
{
    const float* x      = (const float*)d_in[0];
    const float* q_w    = (const float*)d_in[1];
    const float* q_b    = (const float*)d_in[2];
    const float* k_w    = (const float*)d_in[3];
    const float* v_w    = (const float*)d_in[4];
    const float* v_b    = (const float*)d_in[5];
    const float* proj_w = (const float*)d_in[6];
    const float* proj_b = (const float*)d_in[7];
    const float* tau    = (const float*)d_in[8];
    const float* cpb_w1 = (const float*)d_in[9];
    const float* cpb_b1 = (const float*)d_in[10];
    const float* cpb_w2 = (const float*)d_in[11];
    const float* cpb_b2 = (const float*)d_in[12];
    const float* n1g    = (const float*)d_in[13];
    const float* n1b    = (const float*)d_in[14];
    const float* n2g    = (const float*)d_in[15];
    const float* n2b    = (const float*)d_in[16];
    const float* w1     = (const float*)d_in[17];
    const float* b1     = (const float*)d_in[18];
    const float* w2     = (const float*)d_in[19];
    const float* b2     = (const float*)d_in[20];
    float* out = (float*)d_out;

    float *xwf, *q, *v, *hf, *wrf, *tbl, *qkvb;
    cudaGetSymbolAddress((void**)&xwf,  g_xw);
    cudaGetSymbolAddress((void**)&q,    g_q);
    cudaGetSymbolAddress((void**)&v,    g_v);
    cudaGetSymbolAddress((void**)&hf,   g_h);
    cudaGetSymbolAddress((void**)&wrf,  g_wr);
    cudaGetSymbolAddress((void**)&tbl,  g_tbl);
    cudaGetSymbolAddress((void**)&qkvb, g_qkvb);

    uint32_t* xw   = (uint32_t*)xwf;
    uint32_t* qkvh = (uint32_t*)hf;
    uint32_t* hb   = (uint32_t*)(hf + 50331648);
    uint32_t* wr   = (uint32_t*)wrf;

    uint32_t* wqkv = wr;                 // [512][768] u32
    uint32_t* wp   = wr + 393216;        // [512][256]
    uint32_t* wf1  = wr + 524288;        // [512][1024]
    uint32_t* wf2  = wr + 1048576;       // [2048][256]

    cudaFuncSetAttribute((const void*)mma_gemm<0, 0>,
                         cudaFuncAttributeMaxDynamicSharedMemorySize, GEMM_SMEM);
    cudaFuncSetAttribute((const void*)mma_gemm<0, 1>,
                         cudaFuncAttributeMaxDynamicSharedMemorySize, GEMM_SMEM);
    cudaFuncSetAttribute((const void*)mma_gemm<1, 1>,
                         cudaFuncAttributeMaxDynamicSharedMemorySize, GEMM_SMEM);

    pack_all<<<1542, 256>>>(q_w, k_w, v_w, proj_w, w1, w2, q_b, v_b,
                            wqkv, wp, wf1, wf2, qkvb);
    cpb_kernel<<<225, 512>>>(cpb_w1, cpb_b1, cpb_w2, cpb_b2, tbl);
    gather_xw<<<(NROW * 128) / 256, 256>>>(x, xw);

    mma_gemm<0, 1><<<dim3(12, 512), 256, GEMM_SMEM>>>(xw, wqkv, qkvb, qkvh, 1536, 512);
    attn_tc<<<16384, 128>>>(qkvh, tau, tbl, xw);
    mma_gemm<0, 0><<<dim3(4, 512), 256, GEMM_SMEM>>>(xw, wp, proj_b, q, 512, 512);
    ln_res_kernel<<<NTOK, 128>>>(q, x, n1g, n1b, v, xw, 1);
    mma_gemm<1, 1><<<dim3(16, 512), 256, GEMM_SMEM>>>(xw, wf1, b1, hb, 2048, 512);
    mma_gemm<0, 0><<<dim3(4, 512), 256, GEMM_SMEM>>>(hb, wf2, b2, q, 512, 2048);
    ln_res_kernel<<<NTOK, 128>>>(q, v, n2g, n2b, out, (uint32_t*)nullptr, 0);
}

// round 12
// speedup vs baseline: 6.0461x; 1.0600x over previous
#include <cuda_runtime.h>
#include <cuda_fp16.h>
#include <math.h>
#include <stdint.h>

// Problem constants
#define B_   16
#define H_   64
#define W_   64
#define C_   512
#define NH_  16
#define HD_  32
#define NTOK 65536
#define NWIN 64
#define NROW 65536

// ---------------- device scratch (allocation-free) ----------------
__device__ float g_xw[(size_t)NROW * C_];    // half activations (u32-packed), reused
__device__ float g_q [(size_t)NROW * C_];    // fp32 proj-out / fc2-out
__device__ float g_v [(size_t)NROW * C_];    // fp32 x1
__device__ float g_h [(size_t)NROW * 2048];  // qkv half (front) + mlp hidden half
__device__ float g_wr[3145728];              // plain-half weights (u32 view)
__device__ float g_tbl[225 * 16];
__device__ float g_qkvb[1536];

// ---------------- helpers ----------------
__device__ __forceinline__ uint32_t smem_u32(const void* p) {
    uint32_t a;
    asm("{ .reg .u64 t; cvta.to.shared.u64 t, %1; cvt.u32.u64 %0, t; }" : "=r"(a) : "l"(p));
    return a;
}
__device__ __forceinline__ uint32_t packh2(float lo, float hi) {
    __half2 h = __floats2half2_rn(lo, hi);
    return *reinterpret_cast<uint32_t*>(&h);
}
__device__ __forceinline__ void cp16r(uint32_t saddr, const void* gsrc) {
    asm volatile("cp.async.cg.shared.global [%0], [%1], 16;" :: "r"(saddr), "l"(gsrc) : "memory");
}
#define CP_COMMIT() asm volatile("cp.async.commit_group;" ::: "memory")
#define CP_WAIT1()  asm volatile("cp.async.wait_group 1;" ::: "memory")

__device__ __forceinline__ void ldsm4(const void* p, uint32_t* r) {
    uint32_t a = smem_u32(p);
    asm volatile("ldmatrix.sync.aligned.m8n8.x4.shared.b16 {%0,%1,%2,%3}, [%4];"
        : "=r"(r[0]), "=r"(r[1]), "=r"(r[2]), "=r"(r[3]) : "r"(a));
}
__device__ __forceinline__ void ldsm4t(const void* p, uint32_t* r) {
    uint32_t a = smem_u32(p);
    asm volatile("ldmatrix.sync.aligned.m8n8.x4.trans.shared.b16 {%0,%1,%2,%3}, [%4];"
        : "=r"(r[0]), "=r"(r[1]), "=r"(r[2]), "=r"(r[3]) : "r"(a));
}
__device__ __forceinline__ void mma_f16(float* c, uint32_t a0, uint32_t a1,
                                        uint32_t a2, uint32_t a3,
                                        uint32_t b0, uint32_t b1) {
    asm volatile(
        "mma.sync.aligned.m16n8k16.row.col.f32.f16.f16.f32 "
        "{%0,%1,%2,%3}, {%4,%5,%6,%7}, {%8,%9}, {%0,%1,%2,%3};"
        : "+f"(c[0]), "+f"(c[1]), "+f"(c[2]), "+f"(c[3])
        : "r"(a0), "r"(a1), "r"(a2), "r"(a3), "r"(b0), "r"(b1));
}
__device__ __forceinline__ float gelu_f(float t) {
    return 0.5f * t * (1.0f + tanhf(0.7978845608028654f * (t + 0.044715f * t * t * t)));
}

// ---------------- merged prep: all weights f32 -> plain half, + fused bias ---
__device__ __forceinline__ void pack_one(const float* __restrict__ src, uint32_t* __restrict__ dst,
                                         int N, int dstN2, int coloff, int local)
{
    int n8c = N >> 3;
    int k = local / n8c, n8 = local % n8c;
    const float4* s = (const float4*)(src + (size_t)k * N + (n8 << 3));
    float4 f0 = s[0], f1 = s[1];
    uint4 u;
    u.x = packh2(f0.x, f0.y);
    u.y = packh2(f0.z, f0.w);
    u.z = packh2(f1.x, f1.y);
    u.w = packh2(f1.z, f1.w);
    *(uint4*)(dst + (size_t)k * dstN2 + coloff + (n8 << 2)) = u;
}

__global__ void pack_all(const float* __restrict__ q_w, const float* __restrict__ k_w,
                         const float* __restrict__ v_w, const float* __restrict__ p_w,
                         const float* __restrict__ w1, const float* __restrict__ w2,
                         const float* __restrict__ qb, const float* __restrict__ vb,
                         uint32_t* __restrict__ wqkv, uint32_t* __restrict__ wp,
                         uint32_t* __restrict__ wf1, uint32_t* __restrict__ wf2,
                         float* __restrict__ qkvb)
{
    int idx = blockIdx.x * 256 + threadIdx.x;
    if (idx < 32768)        pack_one(q_w, wqkv, 512, 768, 0,   idx);
    else if (idx < 65536)   pack_one(k_w, wqkv, 512, 768, 256, idx - 32768);
    else if (idx < 98304)   pack_one(v_w, wqkv, 512, 768, 512, idx - 65536);
    else if (idx < 131072)  pack_one(p_w, wp,   512, 256, 0,   idx - 98304);
    else if (idx < 262144)  pack_one(w1,  wf1, 2048, 1024, 0,  idx - 131072);
    else if (idx < 393216)  pack_one(w2,  wf2,  512, 256, 0,   idx - 262144);
    else if (idx < 394752) {
        int i = idx - 393216;
        float v = 0.0f;
        if (i < 512) v = qb[i];
        else if (i >= 1024) v = vb[i - 1024];
        qkvb[i] = v;
    }
}

// ---------------- fp16 mma.sync GEMM: K-chunk 64, 3 stages, ptr induction ---
#define AS_U 36                       // u32 per A smem row (32 data + 4 pad)
#define BS_U 68                       // u32 per B smem k-row (64 data + 4 pad)
#define SA_U (128 * AS_U)             // 4608 u32
#define SB_U (64 * BS_U)              // 4352 u32
#define STG_U (SA_U + SB_U)           // 8960 u32
#define STG_B (STG_U * 4)             // 35840 B
#define GEMM_SMEM (3 * STG_B)         // 107520 B
#define ARB (32 * AS_U * 4)           // bytes between A staging row groups
#define BRB (16 * BS_U * 4)           // bytes between B staging row groups

template<int GELU, int HALF_OUT>
__global__ void __launch_bounds__(256, 2) mma_gemm(
    const uint32_t* __restrict__ A, const uint32_t* __restrict__ B,
    const float* __restrict__ bias, void* __restrict__ Cv,
    int N, int K)
{
    extern __shared__ uint32_t smem[];
    const uint32_t sbase = smem_u32(smem);
    const int tid = threadIdx.x;
    const int wid = tid >> 5, lane = tid & 31;
    const int g = lane >> 2, t = lane & 3;
    const int lq = lane & 15, lh = lane >> 4;
    const int wm = wid >> 2, wn = wid & 3;
    const int mw = wm * 64, nw = wn * 32;
    const int m0 = blockIdx.y * 128, n0 = blockIdx.x * 128;
    const int K2 = K >> 1, N2 = N >> 1;
    const int n0u = n0 >> 1, nwu = nw >> 1;

    // ---- staging state (pointer induction; sbase included in smem addrs) ----
    const uint32_t* aptr = A + (size_t)(m0 + (tid >> 3)) * K2 + ((tid & 7) << 2);
    const uint32_t* bptr = B + (size_t)(tid >> 4) * N2 + n0u + ((tid & 15) << 2);
    const size_t aRow = (size_t)32 * K2;       // +32 rows (u32 elements)
    const size_t bRow = (size_t)16 * N2;       // +16 k-rows
    const size_t bAdv = (size_t)64 * N2;       // advance per chunk
    const uint32_t saA = sbase + ((tid >> 3) * AS_U + ((tid & 7) << 2)) * 4;
    const uint32_t saB = sbase + (SA_U + (tid >> 4) * BS_U + ((tid & 15) << 2)) * 4;

#define STAGE64(soff) do { \
    cp16r(saA + (soff),           aptr); \
    cp16r(saA + (soff) + ARB,     aptr + aRow); \
    cp16r(saA + (soff) + 2 * ARB, aptr + 2 * aRow); \
    cp16r(saA + (soff) + 3 * ARB, aptr + 3 * aRow); \
    cp16r(saB + (soff),           bptr); \
    cp16r(saB + (soff) + BRB,     bptr + bRow); \
    cp16r(saB + (soff) + 2 * BRB, bptr + 2 * bRow); \
    cp16r(saB + (soff) + 3 * BRB, bptr + 3 * bRow); \
    aptr += 32; bptr += bAdv; } while (0)

    float acc[4][4][4];
#pragma unroll
    for (int i = 0; i < 4; i++)
#pragma unroll
        for (int j = 0; j < 4; j++)
#pragma unroll
            for (int q = 0; q < 4; q++) acc[i][j][q] = 0.0f;

    const int nch = K >> 6;                   // 64-half chunks

    STAGE64(0);        CP_COMMIT();
    STAGE64(STG_B);    CP_COMMIT();

    int curU = 0;                 // u32 offset of compute stage
    int prevB = 2 * STG_B;        // byte offset of prefetch target

    for (int ch = 0; ch < nch; ++ch) {
        CP_WAIT1();
        __syncthreads();
        if (ch + 2 < nch) STAGE64(prevB);
        CP_COMMIT();

        const uint32_t* As = smem + curU;
        const uint32_t* Bsb = As + SA_U;

#pragma unroll
        for (int ksh = 0; ksh < 2; ++ksh) {     // two 32-half k-halves
            const uint32_t* Ah = As + ksh * 16;
            const uint32_t* Bh = Bsb + ksh * 32 * BS_U;

            uint32_t bfr[2][2][4];
#pragma unroll
            for (int ks = 0; ks < 2; ++ks)
#pragma unroll
                for (int nfp = 0; nfp < 2; ++nfp)
                    ldsm4t(&Bh[(ks * 16 + lq) * BS_U + nwu + nfp * 8 + (lh << 2)], bfr[ks][nfp]);

#pragma unroll
            for (int mf = 0; mf < 4; ++mf) {
                uint32_t af[2][4];
#pragma unroll
                for (int ks = 0; ks < 2; ++ks)
                    ldsm4(&Ah[(mw + mf * 16 + lq) * AS_U + ks * 8 + (lh << 2)], af[ks]);
#pragma unroll
                for (int ks = 0; ks < 2; ++ks) {
                    mma_f16(acc[mf][0], af[ks][0], af[ks][1], af[ks][2], af[ks][3],
                            bfr[ks][0][0], bfr[ks][0][1]);
                    mma_f16(acc[mf][1], af[ks][0], af[ks][1], af[ks][2], af[ks][3],
                            bfr[ks][0][2], bfr[ks][0][3]);
                    mma_f16(acc[mf][2], af[ks][0], af[ks][1], af[ks][2], af[ks][3],
                            bfr[ks][1][0], bfr[ks][1][1]);
                    mma_f16(acc[mf][3], af[ks][0], af[ks][1], af[ks][2], af[ks][3],
                            bfr[ks][1][2], bfr[ks][1][3]);
                }
            }
        }

        prevB = curU * 4;
        curU = (curU == 2 * STG_U) ? 0 : curU + STG_U;
    }
#undef STAGE64

    // epilogue
#pragma unroll
    for (int mf = 0; mf < 4; ++mf) {
        const int row = m0 + mw + mf * 16 + g;
#pragma unroll
        for (int nf = 0; nf < 4; ++nf) {
            const int col = n0 + nw + nf * 8 + t * 2;
            float b0 = 0.f, b1 = 0.f;
            if (bias) { b0 = bias[col]; b1 = bias[col + 1]; }
            float c0 = acc[mf][nf][0] + b0, c1 = acc[mf][nf][1] + b1;
            float c2 = acc[mf][nf][2] + b0, c3 = acc[mf][nf][3] + b1;
            if (GELU) { c0 = gelu_f(c0); c1 = gelu_f(c1); c2 = gelu_f(c2); c3 = gelu_f(c3); }
            if (HALF_OUT) {
                uint32_t* Ch = (uint32_t*)Cv;
                Ch[((size_t)row * N + col) >> 1]       = packh2(c0, c1);
                Ch[((size_t)(row + 8) * N + col) >> 1] = packh2(c2, c3);
            } else {
                float* Cf = (float*)Cv;
                *(float2*)(Cf + (size_t)row * N + col)       = make_float2(c0, c1);
                *(float2*)(Cf + (size_t)(row + 8) * N + col) = make_float2(c2, c3);
            }
        }
    }
}

// ---------------- CPB bias table ----------------
__global__ void cpb_kernel(const float* __restrict__ w1, const float* __restrict__ b1,
                           const float* __restrict__ w2, const float* __restrict__ b2,
                           float* __restrict__ tbl)
{
    int f = blockIdx.x;
    int h = threadIdx.x;
    int i = f / 15, j = f % 15;
    float v0 = 8.0f * (float)(j - 7) / 7.0f;
    float v1 = 8.0f * (float)(i - 7) / 7.0f;
    float c0 = copysignf(log2f(fabsf(v0) + 1.0f) * (1.0f / 3.0f), v0);
    float c1 = copysignf(log2f(fabsf(v1) + 1.0f) * (1.0f / 3.0f), v1);
    float hid = fmaxf(c0 * w1[h] + c1 * w1[512 + h] + b1[h], 0.0f);

    __shared__ float red[512];
    for (int nh = 0; nh < 16; ++nh) {
        red[h] = hid * w2[h * 16 + nh];
        __syncthreads();
        for (int s = 256; s > 0; s >>= 1) {
            if (h < s) red[h] += red[h + s];
            __syncthreads();
        }
        if (h == 0) tbl[f * 16 + nh] = red[0] + b2[nh];
        __syncthreads();
    }
}

// ---------------- shift + window partition gather -> half -------------------
__global__ void gather_xw(const float* __restrict__ x, uint32_t* __restrict__ xw)
{
    size_t idx = (size_t)blockIdx.x * 256 + threadIdx.x;
    if (idx >= (size_t)NROW * 128) return;
    int c4  = (int)(idx & 127);
    int row = (int)(idx >> 7);
    int n = row & 63, bw = row >> 6;
    int win = bw & 63, b = bw >> 6;
    int wh = win >> 3, wwn = win & 7;
    int i = n >> 3, j = n & 7;
    int h = ((wh << 3) + i + 4) & 63;
    int w = ((wwn << 3) + j + 4) & 63;
    float4 vv = *(((const float4*)(x + (size_t)((b << 12) + (h << 6) + w) * C_)) + c4);
    uint2 u;
    u.x = packh2(vv.x, vv.y);
    u.y = packh2(vv.z, vv.w);
    *(uint2*)(xw + (size_t)row * 256 + c4 * 2) = u;
}

// ---------------- tensor-core windowed cosine attention ---------------------
__global__ void __launch_bounds__(128) attn_tc(
    const uint32_t* __restrict__ qkv,
    const float* __restrict__ tau, const float* __restrict__ tbl,
    uint32_t* __restrict__ out)
{
    __shared__ uint32_t Qh[64 * 17];
    __shared__ uint32_t Kh[64 * 17];
    __shared__ __half sVt[32 * 72];
    __shared__ float qn[64], kn[64];

    const int blk = blockIdx.x;
    const int head = blk & 15, bw = blk >> 4;
    const int win = bw & 63;
    const int tid = threadIdx.x;
    const int wid = tid >> 5, lane = tid & 31;
    const int g = lane >> 2, t = lane & 3;
    const int mr = wid << 4;

    const uint32_t* base = qkv + (size_t)(bw << 6) * 768 + (head << 4);

    for (int i = tid; i < 1024; i += 128) {
        int tok = i >> 4, c = i & 15;
        Qh[tok * 17 + c] = base[(size_t)tok * 768 + c];
        Kh[tok * 17 + c] = base[(size_t)tok * 768 + 256 + c];
    }
    for (int i = tid; i < 1024; i += 128) {
        int tok = i >> 4, dp = i & 15;
        uint32_t u = base[(size_t)tok * 768 + 512 + dp];
        __half2 h = *(__half2*)&u;
        sVt[(dp * 2) * 72 + tok]     = __low2half(h);
        sVt[(dp * 2 + 1) * 72 + tok] = __high2half(h);
    }
    __syncthreads();

    {
        int tok = tid & 63;
        const uint32_t* src = (tid < 64) ? &Qh[tok * 17] : &Kh[tok * 17];
        float s = 0.0f;
#pragma unroll
        for (int c = 0; c < 16; ++c) {
            float2 f = __half22float2(*(__half2*)&src[c]);
            s = fmaf(f.x, f.x, fmaf(f.y, f.y, s));
        }
        if (tid < 64) qn[tok] = sqrtf(s); else kn[tok] = sqrtf(s);
    }
    __syncthreads();

    float sacc[8][4];
#pragma unroll
    for (int nf = 0; nf < 8; ++nf)
#pragma unroll
        for (int e = 0; e < 4; ++e) sacc[nf][e] = 0.0f;

    uint32_t aq[2][4];
#pragma unroll
    for (int kb = 0; kb < 2; ++kb) {
        aq[kb][0] = Qh[(mr + g) * 17 + kb * 8 + t];
        aq[kb][1] = Qh[(mr + g + 8) * 17 + kb * 8 + t];
        aq[kb][2] = Qh[(mr + g) * 17 + kb * 8 + t + 4];
        aq[kb][3] = Qh[(mr + g + 8) * 17 + kb * 8 + t + 4];
    }
#pragma unroll
    for (int nf = 0; nf < 8; ++nf) {
        const int col = (nf << 3) + g;
#pragma unroll
        for (int kb = 0; kb < 2; ++kb) {
            uint32_t b0 = Kh[col * 17 + kb * 8 + t];
            uint32_t b1 = Kh[col * 17 + kb * 8 + t + 4];
            mma_f16(sacc[nf], aq[kb][0], aq[kb][1], aq[kb][2], aq[kb][3], b0, b1);
        }
    }

    const float ls = fmaxf(tau[head] + 2.302585092994046f, 0.01f);
    const int whb = (win >> 3) << 3, wwb = (win & 7) << 3;
    const int r1 = mr + g, r2 = mr + g + 8;
    float mx1 = -1e30f, mx2 = -1e30f;
#pragma unroll
    for (int nf = 0; nf < 8; ++nf) {
#pragma unroll
        for (int e = 0; e < 4; ++e) {
            const int r = (e < 2) ? r1 : r2;
            const int c = (nf << 3) + (t << 1) + (e & 1);
            float a = sacc[nf][e] / fmaxf(qn[r] * kn[c], 1e-6f) * ls;
            int dr = (r >> 3) - (c >> 3), dc = (r & 7) - (c & 7);
            float bsv = tbl[((dr + 7) * 15 + (dc + 7)) * 16 + head];
            a += 16.0f / (1.0f + expf(-bsv));
            int hn = whb + (r >> 3), wn = wwb + (r & 7);
            int hm = whb + (c >> 3), wm = wwb + (c & 7);
            int rn = (hn < 56 ? 0 : (hn < 60 ? 1 : 2)) * 3 + (wn < 56 ? 0 : (wn < 60 ? 1 : 2));
            int rm = (hm < 56 ? 0 : (hm < 60 ? 1 : 2)) * 3 + (wm < 56 ? 0 : (wm < 60 ? 1 : 2));
            if (rn != rm) a -= 100.0f;
            sacc[nf][e] = a;
            if (e < 2) mx1 = fmaxf(mx1, a); else mx2 = fmaxf(mx2, a);
        }
    }
#pragma unroll
    for (int o = 1; o <= 2; o <<= 1) {
        mx1 = fmaxf(mx1, __shfl_xor_sync(0xffffffffu, mx1, o));
        mx2 = fmaxf(mx2, __shfl_xor_sync(0xffffffffu, mx2, o));
    }
    float s1 = 0.0f, s2 = 0.0f;
#pragma unroll
    for (int nf = 0; nf < 8; ++nf) {
        float e0 = expf(sacc[nf][0] - mx1);
        float e1 = expf(sacc[nf][1] - mx1);
        float e2 = expf(sacc[nf][2] - mx2);
        float e3 = expf(sacc[nf][3] - mx2);
        sacc[nf][0] = e0; sacc[nf][1] = e1; sacc[nf][2] = e2; sacc[nf][3] = e3;
        s1 += e0 + e1; s2 += e2 + e3;
    }
#pragma unroll
    for (int o = 1; o <= 2; o <<= 1) {
        s1 += __shfl_xor_sync(0xffffffffu, s1, o);
        s2 += __shfl_xor_sync(0xffffffffu, s2, o);
    }
    const float inv1 = 1.0f / s1, inv2 = 1.0f / s2;

    float oacc[4][4];
#pragma unroll
    for (int nf = 0; nf < 4; ++nf)
#pragma unroll
        for (int e = 0; e < 4; ++e) oacc[nf][e] = 0.0f;

    const uint32_t* vt32 = (const uint32_t*)sVt;
#pragma unroll
    for (int kc = 0; kc < 4; ++kc) {
        uint32_t a0 = packh2(sacc[kc * 2][0],     sacc[kc * 2][1]);
        uint32_t a1 = packh2(sacc[kc * 2][2],     sacc[kc * 2][3]);
        uint32_t a2 = packh2(sacc[kc * 2 + 1][0], sacc[kc * 2 + 1][1]);
        uint32_t a3 = packh2(sacc[kc * 2 + 1][2], sacc[kc * 2 + 1][3]);
#pragma unroll
        for (int nf = 0; nf < 4; ++nf) {
            const int d = (nf << 3) + g;
            uint32_t b0 = vt32[d * 36 + kc * 8 + t];
            uint32_t b1 = vt32[d * 36 + kc * 8 + t + 4];
            mma_f16(oacc[nf], a0, a1, a2, a3, b0, b1);
        }
    }

    const size_t orow1 = (size_t)((bw << 6) + r1) * 256 + (head << 4);
    const size_t orow2 = (size_t)((bw << 6) + r2) * 256 + (head << 4);
#pragma unroll
    for (int nf = 0; nf < 4; ++nf) {
        out[orow1 + (nf << 2) + t] = packh2(oacc[nf][0] * inv1, oacc[nf][1] * inv1);
        out[orow2 + (nf << 2) + t] = packh2(oacc[nf][2] * inv2, oacc[nf][3] * inv2);
    }
}

// ---------------- (optional gather) + LayerNorm + residual ----------------
__global__ void __launch_bounds__(128) ln_res_kernel(
    const float* __restrict__ src, const float* __restrict__ resid,
    const float* __restrict__ g, const float* __restrict__ bb,
    float* __restrict__ dst, uint32_t* __restrict__ dst_half, int gather)
{
    int r = blockIdx.x, tid = threadIdx.x;
    int srow = r;
    if (gather) {
        int b = r >> 12, hw = r & 4095;
        int h = hw >> 6, w = hw & 63;
        int hh = (h + 60) & 63, wv = (w + 60) & 63;
        srow = (((b << 6) + ((hh >> 3) << 3) + (wv >> 3)) << 6) + ((hh & 7) << 3) + (wv & 7);
    }
    float4 val = ((const float4*)(src + (size_t)srow * C_))[tid];
    __shared__ float sh[4];

    float s = val.x + val.y + val.z + val.w;
#pragma unroll
    for (int o = 16; o; o >>= 1) s += __shfl_xor_sync(0xffffffffu, s, o);
    if ((tid & 31) == 0) sh[tid >> 5] = s;
    __syncthreads();
    float mean = (sh[0] + sh[1] + sh[2] + sh[3]) * (1.0f / 512.0f);
    __syncthreads();

    float dx = val.x - mean, dy = val.y - mean, dz = val.z - mean, dw = val.w - mean;
    float s2 = dx * dx + dy * dy + dz * dz + dw * dw;
#pragma unroll
    for (int o = 16; o; o >>= 1) s2 += __shfl_xor_sync(0xffffffffu, s2, o);
    if ((tid & 31) == 0) sh[tid >> 5] = s2;
    __syncthreads();
    float var = (sh[0] + sh[1] + sh[2] + sh[3]) * (1.0f / 512.0f);
    float rstd = rsqrtf(var + 1e-6f);

    float4 gg = ((const float4*)g)[tid];
    float4 bv = ((const float4*)bb)[tid];
    float4 xr = ((const float4*)(resid + (size_t)r * C_))[tid];
    float4 o;
    o.x = xr.x + dx * rstd * gg.x + bv.x;
    o.y = xr.y + dy * rstd * gg.y + bv.y;
    o.z = xr.z + dz * rstd * gg.z + bv.z;
    o.w = xr.w + dw * rstd * gg.w + bv.w;
    ((float4*)(dst + (size_t)r * C_))[tid] = o;
    if (dst_half) {
        uint2 u;
        u.x = packh2(o.x, o.y);
        u.y = packh2(o.z, o.w);
        *(uint2*)(dst_half + (size_t)r * 256 + tid * 2) = u;
    }
}

// ---------------- host launch ----------------
extern "C" void kernel_launch(void* const* d_in, const int* in_sizes, int n_in,
                              void* d_out, int out_size)
{
    const float* x      = (const float*)d_in[0];
    const float* q_w    = (const float*)d_in[1];
    const float* q_b    = (const float*)d_in[2];
    const float* k_w    = (const float*)d_in[3];
    const float* v_w    = (const float*)d_in[4];
    const float* v_b    = (const float*)d_in[5];
    const float* proj_w = (const float*)d_in[6];
    const float* proj_b = (const float*)d_in[7];
    const float* tau    = (const float*)d_in[8];
    const float* cpb_w1 = (const float*)d_in[9];
    const float* cpb_b1 = (const float*)d_in[10];
    const float* cpb_w2 = (const float*)d_in[11];
    const float* cpb_b2 = (const float*)d_in[12];
    const float* n1g    = (const float*)d_in[13];
    const float* n1b    = (const float*)d_in[14];
    const float* n2g    = (const float*)d_in[15];
    const float* n2b    = (const float*)d_in[16];
    const float* w1     = (const float*)d_in[17];
    const float* b1     = (const float*)d_in[18];
    const float* w2     = (const float*)d_in[19];
    const float* b2     = (const float*)d_in[20];
    float* out = (float*)d_out;

    float *xwf, *q, *v, *hf, *wrf, *tbl, *qkvb;
    cudaGetSymbolAddress((void**)&xwf,  g_xw);
    cudaGetSymbolAddress((void**)&q,    g_q);
    cudaGetSymbolAddress((void**)&v,    g_v);
    cudaGetSymbolAddress((void**)&hf,   g_h);
    cudaGetSymbolAddress((void**)&wrf,  g_wr);
    cudaGetSymbolAddress((void**)&tbl,  g_tbl);
    cudaGetSymbolAddress((void**)&qkvb, g_qkvb);

    uint32_t* xw   = (uint32_t*)xwf;
    uint32_t* qkvh = (uint32_t*)hf;
    uint32_t* hb   = (uint32_t*)(hf + 50331648);
    uint32_t* wr   = (uint32_t*)wrf;

    uint32_t* wqkv = wr;                 // [512][768] u32
    uint32_t* wp   = wr + 393216;        // [512][256]
    uint32_t* wf1  = wr + 524288;        // [512][1024]
    uint32_t* wf2  = wr + 1048576;       // [2048][256]

    cudaFuncSetAttribute((const void*)mma_gemm<0, 0>,
                         cudaFuncAttributeMaxDynamicSharedMemorySize, GEMM_SMEM);
    cudaFuncSetAttribute((const void*)mma_gemm<0, 1>,
                         cudaFuncAttributeMaxDynamicSharedMemorySize, GEMM_SMEM);
    cudaFuncSetAttribute((const void*)mma_gemm<1, 1>,
                         cudaFuncAttributeMaxDynamicSharedMemorySize, GEMM_SMEM);

    pack_all<<<1542, 256>>>(q_w, k_w, v_w, proj_w, w1, w2, q_b, v_b,
                            wqkv, wp, wf1, wf2, qkvb);
    cpb_kernel<<<225, 512>>>(cpb_w1, cpb_b1, cpb_w2, cpb_b2, tbl);
    gather_xw<<<(NROW * 128) / 256, 256>>>(x, xw);

    mma_gemm<0, 1><<<dim3(12, 512), 256, GEMM_SMEM>>>(xw, wqkv, qkvb, qkvh, 1536, 512);
    attn_tc<<<16384, 128>>>(qkvh, tau, tbl, xw);
    mma_gemm<0, 0><<<dim3(4, 512), 256, GEMM_SMEM>>>(xw, wp, proj_b, q, 512, 512);
    ln_res_kernel<<<NTOK, 128>>>(q, x, n1g, n1b, v, xw, 1);
    mma_gemm<1, 1><<<dim3(16, 512), 256, GEMM_SMEM>>>(xw, wf1, b1, hb, 2048, 512);
    mma_gemm<0, 0><<<dim3(4, 512), 256, GEMM_SMEM>>>(hb, wf2, b2, q, 512, 2048);
    ln_res_kernel<<<NTOK, 128>>>(q, v, n2g, n2b, out, (uint32_t*)nullptr, 0);
}